// round 5
// baseline (speedup 1.0000x reference)
#include <cuda_runtime.h>

#define NT 224

// shared-memory layout (float offsets)
#define OFF_A    0        // 7776  MPO ping / row ping-pong / R / warp partials
#define OFF_B    7776     // 7776  MPO pong / env0 / env_top / L2
#define OFF_N    15552    // 2592  node double-buffer: H0, H1
#define OFF_RED  18144    // 8
#define OFF_OUT  18152    // 12
#define OFF_X    18164    // 32
#define SMEM_FLOATS 18208
#define SMEM_BYTES  (SMEM_FLOATS * 4)

#define H0 (OFF_N)
#define H1 (OFF_N + 1296)

extern __shared__ float sm[];

// ---------------------------------------------------------------------------
// sumsq all-reduce
// ---------------------------------------------------------------------------

__device__ __forceinline__ void sumsq_publish(float v, int tid)
{
    #pragma unroll
    for (int o = 16; o > 0; o >>= 1) v += __shfl_down_sync(0xffffffffu, v, o);
    if ((tid & 31) == 0) sm[OFF_RED + (tid >> 5)] = v;
}

__device__ __forceinline__ float read_scale()
{
    float s = 0.0f;
    #pragma unroll
    for (int w = 0; w < 7; w++) s += sm[OFF_RED + w];
    return rsqrtf(s);
}

// ---------------------------------------------------------------------------
// node prefetch: COALESCED global reads (source-linear), permuted smem stores
// node = x0 * P[addr] + x1 * P[addr + 1296];  source tensor layout [u][r][d][l]
// ---------------------------------------------------------------------------

// -- full node (n11, n12, n21): read linear k, store [u][l][d][r] --
__device__ __forceinline__ void pf_full(float* v, const float* __restrict__ P,
                                        float x0, float x1, int tid)
{
    #pragma unroll
    for (int i = 0; i < 6; i++) {
        int k = tid + i * NT;
        if (k < 1296) v[i] = x0 * __ldg(P + k) + x1 * __ldg(P + k + 1296);
    }
}

__device__ __forceinline__ void st_full(int off, const float* v, int tid)
{
    #pragma unroll
    for (int i = 0; i < 6; i++) {
        int k = tid + i * NT;
        if (k < 1296) {
            int u = k / 216, rem = k % 216;
            int r = rem / 36;
            int d = (rem / 6) % 6;
            int l = rem % 6;
            sm[off + u * 216 + l * 36 + d * 6 + r] = v[i];
        }
    }
}

// -- n10 / n20 (slice l=0): enumerate (u,r,d) source order; store [u][d][r] --
__device__ __forceinline__ float pf_l0(const float* __restrict__ P,
                                       float x0, float x1, int tid)
{
    if (tid >= 216) return 0.0f;
    int u = tid / 36, r = (tid / 6) % 6, d = tid % 6;
    int addr = u * 216 + r * 36 + d * 6;
    return x0 * __ldg(P + addr) + x1 * __ldg(P + addr + 1296);
}

__device__ __forceinline__ void st_l0(int off, float v, int tid, float scale)
{
    if (tid < 216) {
        int u = tid / 36, r = (tid / 6) % 6, d = tid % 6;
        sm[off + u * 36 + d * 6 + r] = v * scale;
    }
}

// -- n13 (slice r=0): contiguous per-u source reads; store [u][l][d] --
__device__ __forceinline__ float pf_r0(const float* __restrict__ P,
                                       float x0, float x1, int tid)
{
    if (tid >= 216) return 0.0f;
    int u = tid / 36, rest = tid % 36;        // rest = d*6 + l
    int addr = u * 216 + rest;
    return x0 * __ldg(P + addr) + x1 * __ldg(P + addr + 1296);
}

__device__ __forceinline__ void st_n13(int off, float v, int tid)
{
    if (tid < 216) {
        int u = tid / 36, rest = tid % 36;
        int d = rest / 6, l = rest % 6;
        sm[off + u * 36 + l * 6 + d] = v;
    }
}

// -- n23 (slice r=0): identity on (d,l); store [u][d][l] --
__device__ __forceinline__ void st_n23(int off, float v, int tid, float scale)
{
    if (tid < 216) sm[off + tid] = v * scale;   // tid = u*36 + d*6 + l
}

// -- n01/n02 (slice u=0): identity, contiguous --
__device__ __forceinline__ float pf_u0(const float* __restrict__ P,
                                       float x0, float x1, int tid)
{
    if (tid >= 216) return 0.0f;
    return x0 * __ldg(P + tid) + x1 * __ldg(P + tid + 1296);
}

__device__ __forceinline__ void st_id(int off, float v, int n, int tid)
{
    if (tid < n) sm[off + tid] = v;
}

// -- small 36-elem slices --
__device__ __forceinline__ float pf_slice36(const float* __restrict__ P,
                                            float x0, float x1,
                                            int sa, int sb, int tid)
{
    if (tid >= 36) return 0.0f;
    int a = tid / 6, bb = tid % 6;
    int addr = a * sa + bb * sb;
    return x0 * __ldg(P + addr) + x1 * __ldg(P + addr + 1296);
}

// -- n31/n32 (slice d=0): runs of 6, identity layout [u][r][l] --
__device__ __forceinline__ float pf_d0(const float* __restrict__ P,
                                       float x0, float x1, int tid)
{
    if (tid >= 216) return 0.0f;
    int u = tid / 36, r = (tid / 6) % 6, l = tid % 6;
    int addr = u * 216 + r * 36 + l;
    return x0 * __ldg(P + addr) + x1 * __ldg(P + addr + 1296);
}

// ---------------------------------------------------------------------------
// small-row helpers (rows 0 and 3)
// ---------------------------------------------------------------------------

__device__ __forceinline__ void rowstep(int outOff, int inOff, int nodeOff,
                                        int As, bool swap, int tid)
{
    const int n = As * 36;
    for (int k = tid; k < n; k += NT) {
        int A = k / 36;
        int p = (k / 6) % 6;
        int q = k % 6;
        int nb = (swap ? (p * 6 + q) : (q * 6 + p)) * 6;
        const float2* ip = (const float2*)(sm + inOff + A * 6);
        float2 i01 = ip[0], i23 = ip[1], i45 = ip[2];
        float acc = i01.x * sm[nodeOff + nb + 0] + i01.y * sm[nodeOff + nb + 1]
                  + i23.x * sm[nodeOff + nb + 2] + i23.y * sm[nodeOff + nb + 3]
                  + i45.x * sm[nodeOff + nb + 4] + i45.y * sm[nodeOff + nb + 5];
        sm[outOff + k] = acc;
    }
}

__device__ __forceinline__ float laststep_sq(int outOff, int inOff, int nodeOff, int tid)
{
    float ss = 0.0f;
    for (int k = tid; k < 1296; k += NT) {
        int A = k / 6;
        int p = k % 6;
        const float2* ip = (const float2*)(sm + inOff + A * 6);
        float2 i01 = ip[0], i23 = ip[1], i45 = ip[2];
        const float* nb = sm + nodeOff + p * 6;
        float acc = i01.x * nb[0] + i01.y * nb[1]
                  + i23.x * nb[2] + i23.y * nb[3]
                  + i45.x * nb[4] + i45.y * nb[5];
        ss += acc * acc;
        sm[outOff + k] = acc;
    }
    return ss;
}

__device__ __forceinline__ float laststep_T_sq(int outOff, int inOff, int nodeOff, int tid)
{
    float ss = 0.0f;
    for (int k = tid; k < 1296; k += NT) {
        int A = k / 6;
        int p = k % 6;
        const float2* ip = (const float2*)(sm + inOff + A * 6);
        float2 i01 = ip[0], i23 = ip[1], i45 = ip[2];
        const float* nb = sm + nodeOff + p * 6;
        float acc = i01.x * nb[0] + i01.y * nb[1]
                  + i23.x * nb[2] + i23.y * nb[3]
                  + i45.x * nb[4] + i45.y * nb[5];
        ss += acc * acc;
        sm[outOff + p * 216 + (A / 6) * 6 + (A % 6)] = acc;
    }
    return ss;
}

// ---------------------------------------------------------------------------
// MPO kernels: 3(row) x 12(col) register tiles, 216 threads
// ---------------------------------------------------------------------------

__device__ __forceinline__ void mpo_first36(int outOff, int eOff, int nodeOff, int tid)
{
    if (tid >= 216) return;
    const int rg = tid / 3;
    const int cg = tid % 3;
    float acc[3][12];
    #pragma unroll
    for (int rr = 0; rr < 3; rr++)
        #pragma unroll
        for (int j = 0; j < 12; j++) acc[rr][j] = 0.0f;
    #pragma unroll 1
    for (int u = 0; u < 6; u++) {
        float e[3];
        #pragma unroll
        for (int rr = 0; rr < 3; rr++) e[rr] = sm[eOff + u * 216 + rg * 3 + rr];
        const float4* nb = (const float4*)(sm + nodeOff + u * 36 + cg * 12);
        float4 n0 = nb[0], n1 = nb[1], n2 = nb[2];
        #pragma unroll
        for (int rr = 0; rr < 3; rr++) {
            acc[rr][0] += e[rr] * n0.x; acc[rr][1]  += e[rr] * n0.y;
            acc[rr][2] += e[rr] * n0.z; acc[rr][3]  += e[rr] * n0.w;
            acc[rr][4] += e[rr] * n1.x; acc[rr][5]  += e[rr] * n1.y;
            acc[rr][6] += e[rr] * n1.z; acc[rr][7]  += e[rr] * n1.w;
            acc[rr][8] += e[rr] * n2.x; acc[rr][9]  += e[rr] * n2.y;
            acc[rr][10]+= e[rr] * n2.z; acc[rr][11] += e[rr] * n2.w;
        }
    }
    #pragma unroll
    for (int rr = 0; rr < 3; rr++) {
        float4* out = (float4*)(sm + outOff + (rg * 3 + rr) * 36 + cg * 12);
        out[0] = make_float4(acc[rr][0], acc[rr][1], acc[rr][2], acc[rr][3]);
        out[1] = make_float4(acc[rr][4], acc[rr][5], acc[rr][6], acc[rr][7]);
        out[2] = make_float4(acc[rr][8], acc[rr][9], acc[rr][10], acc[rr][11]);
    }
}

__device__ __forceinline__ void mpo_full36(int outOff, int inOff, int nodeOff, int tid)
{
    if (tid >= 216) return;
    const int rg = tid / 3;
    const int cg = tid % 3;
    float acc[3][12];
    #pragma unroll
    for (int rr = 0; rr < 3; rr++)
        #pragma unroll
        for (int j = 0; j < 12; j++) acc[rr][j] = 0.0f;
    #pragma unroll 1
    for (int u = 0; u < 6; u++) {
        float a[3][6];
        #pragma unroll
        for (int rr = 0; rr < 3; rr++) {
            const float2* sp = (const float2*)(sm + inOff + u * 1296 + (rg * 3 + rr) * 6);
            float2 s01 = sp[0], s23 = sp[1], s45 = sp[2];
            a[rr][0] = s01.x; a[rr][1] = s01.y;
            a[rr][2] = s23.x; a[rr][3] = s23.y;
            a[rr][4] = s45.x; a[rr][5] = s45.y;
        }
        #pragma unroll
        for (int x = 0; x < 6; x++) {
            const float4* nb = (const float4*)(sm + nodeOff + (u * 6 + x) * 36 + cg * 12);
            float4 n0 = nb[0], n1 = nb[1], n2 = nb[2];
            #pragma unroll
            for (int rr = 0; rr < 3; rr++) {
                float sv = a[rr][x];
                acc[rr][0] += sv * n0.x; acc[rr][1]  += sv * n0.y;
                acc[rr][2] += sv * n0.z; acc[rr][3]  += sv * n0.w;
                acc[rr][4] += sv * n1.x; acc[rr][5]  += sv * n1.y;
                acc[rr][6] += sv * n1.z; acc[rr][7]  += sv * n1.w;
                acc[rr][8] += sv * n2.x; acc[rr][9]  += sv * n2.y;
                acc[rr][10]+= sv * n2.z; acc[rr][11] += sv * n2.w;
            }
        }
    }
    #pragma unroll
    for (int rr = 0; rr < 3; rr++) {
        float4* out = (float4*)(sm + outOff + (rg * 3 + rr) * 36 + cg * 12);
        out[0] = make_float4(acc[rr][0], acc[rr][1], acc[rr][2], acc[rr][3]);
        out[1] = make_float4(acc[rr][4], acc[rr][5], acc[rr][6], acc[rr][7]);
        out[2] = make_float4(acc[rr][8], acc[rr][9], acc[rr][10], acc[rr][11]);
    }
}

__device__ __forceinline__ float mpo_last36_sq(int outOff, int inOff, int nodeOff, int tid)
{
    if (tid >= 216) return 0.0f;
    float acc[6] = {0, 0, 0, 0, 0, 0};
    #pragma unroll 1
    for (int u = 0; u < 6; u++) {
        const float2* sp = (const float2*)(sm + inOff + u * 1296 + tid * 6);
        float2 s01 = sp[0], s23 = sp[1], s45 = sp[2];
        float sx[6] = {s01.x, s01.y, s23.x, s23.y, s45.x, s45.y};
        #pragma unroll
        for (int x = 0; x < 6; x++) {
            float sv = sx[x];
            const float2* nb = (const float2*)(sm + nodeOff + (u * 6 + x) * 6);
            float2 n01 = nb[0], n23 = nb[1], n45 = nb[2];
            acc[0] += sv * n01.x; acc[1] += sv * n01.y;
            acc[2] += sv * n23.x; acc[3] += sv * n23.y;
            acc[4] += sv * n45.x; acc[5] += sv * n45.y;
        }
    }
    float2* out = (float2*)(sm + outOff + tid * 6);
    out[0] = make_float2(acc[0], acc[1]);
    out[1] = make_float2(acc[2], acc[3]);
    out[2] = make_float2(acc[4], acc[5]);
    float ss = 0.0f;
    #pragma unroll
    for (int i = 0; i < 6; i++) ss += acc[i] * acc[i];
    return ss;
}

__device__ __noinline__ void rstep36(int outOff, int ebOff, int nodeOff, int tid)
{
    if (tid >= 216) return;
    int u3 = tid / 36;
    int dd = tid % 36;
    float acc[36];
    #pragma unroll
    for (int i = 0; i < 36; i++) acc[i] = 0.0f;
    #pragma unroll 1
    for (int d3 = 0; d3 < 6; d3++) {
        const float2* ep = (const float2*)(sm + ebOff + d3 * 216 + dd * 6);
        float2 e01 = ep[0], e23 = ep[1], e45 = ep[2];
        float eb[6] = {e01.x, e01.y, e23.x, e23.y, e45.x, e45.y};
        const float2* np = (const float2*)(sm + nodeOff + u3 * 36 + d3 * 6);
        float2 n01 = np[0], n23v = np[1], n45 = np[2];
        float nv[6] = {n01.x, n01.y, n23v.x, n23v.y, n45.x, n45.y};
        #pragma unroll
        for (int d2 = 0; d2 < 6; d2++)
            #pragma unroll
            for (int l3 = 0; l3 < 6; l3++)
                acc[d2 * 6 + l3] += eb[d2] * nv[l3];
    }
    float4* out = (float4*)(sm + outOff + tid * 36);
    #pragma unroll
    for (int q = 0; q < 9; q++)
        out[q] = make_float4(acc[q*4], acc[q*4+1], acc[q*4+2], acc[q*4+3]);
}

__device__ __noinline__ void tgemm_tiled(int tOff, int lOff, int rOff, int tid)
{
    if (tid >= 162) return;
    int pr = tid / 9;
    int bt = tid % 9;
    int u  = pr / 3;
    int l0 = (pr % 3) * 2;
    int b0 = bt * 4;
    float acc[8];
    #pragma unroll
    for (int i = 0; i < 8; i++) acc[i] = 0.0f;
    const float* Lp = sm + lOff + u * 1296 + l0;
    const float* Rp = sm + rOff + b0;
    #pragma unroll 4
    for (int m = 0; m < 216; m++) {
        float2 a  = *(const float2*)(Lp + m * 6);
        float4 bv = *(const float4*)(Rp + m * 36);
        acc[0] += a.x * bv.x; acc[1] += a.x * bv.y;
        acc[2] += a.x * bv.z; acc[3] += a.x * bv.w;
        acc[4] += a.y * bv.x; acc[5] += a.y * bv.y;
        acc[6] += a.y * bv.z; acc[7] += a.y * bv.w;
    }
    #pragma unroll
    for (int j = 0; j < 4; j++) {
        int beta = b0 + j;
        int d = beta / 6;
        int r = beta % 6;
        sm[tOff + u * 216 + r * 36 + d * 6 + l0]     = acc[j];
        sm[tOff + u * 216 + r * 36 + d * 6 + l0 + 1] = acc[4 + j];
    }
}

// ---------------------------------------------------------------------------
// kernel
// ---------------------------------------------------------------------------

__global__ __launch_bounds__(NT, 3)
void peps_forward_kernel(const float* __restrict__ inputs,
                         const float* __restrict__ peps,
                         const float* __restrict__ pepsc,
                         float* __restrict__ out, int B)
{
    const int tid = threadIdx.x;
    const int b = blockIdx.x;

    if (tid < 32) sm[OFF_X + tid] = inputs[b * 32 + tid];
    __syncthreads();

    #define PB(i, j)  (peps + ((i) * 4 + (j)) * 2 * 1296)
    #define XX0(i, j) sm[OFF_X + ((i) * 4 + (j)) * 2]
    #define XX1(i, j) sm[OFF_X + ((i) * 4 + (j)) * 2 + 1]

    const int P0 = OFF_A;
    const int P1 = OFF_A + 1296;
    float vf[6];

    // ---- init: n00 (u=0,l=0, transposed into P0) + n01 -> H1 ----
    {
        float v00 = pf_slice36(PB(0, 0), XX0(0, 0), XX1(0, 0), 36, 6, tid); // (r,d)
        float v01 = pf_u0(PB(0, 1), XX0(0, 1), XX1(0, 1), tid);
        if (tid < 36) sm[P0 + (tid % 6) * 6 + (tid / 6)] = v00;  // P0[d*6+r]
        st_id(H1, v01, 216, tid);
    }
    __syncthreads();
    // step: rowstep with n01; prefetch n02
    {
        float v = pf_u0(PB(0, 2), XX0(0, 2), XX1(0, 2), tid);
        rowstep(P1, P0, H1, 6, false, tid);
        st_id(H0, v, 216, tid);
    }
    __syncthreads();
    // step: rowstep with n02; prefetch n03 (u=0,r=0 -> (d,l) identity)
    {
        float v = pf_slice36(PB(0, 3), XX0(0, 3), XX1(0, 3), 6, 1, tid);
        rowstep(P0, P1, H0, 36, false, tid);
        st_id(H1, v, 36, tid);
    }
    __syncthreads();
    // step: env0 raw -> B ; scale into n10 [u][d][r]
    {
        float v = pf_l0(PB(1, 0), XX0(1, 0), XX1(1, 0), tid);
        float ss = laststep_sq(OFF_B, P0, H1, tid);
        sumsq_publish(ss, tid);
        __syncthreads();
        float sc = read_scale();
        st_l0(H0, v, tid, sc);
    }
    __syncthreads();

    // ================= Row 1 =================
    {
        pf_full(vf, PB(1, 1), XX0(1, 1), XX1(1, 1), tid);
        mpo_first36(OFF_A, OFF_B, H0, tid);
        st_full(H1, vf, tid);
    }
    __syncthreads();
    {
        pf_full(vf, PB(1, 2), XX0(1, 2), XX1(1, 2), tid);
        mpo_full36(OFF_B, OFF_A, H1, tid);
        st_full(H0, vf, tid);
    }
    __syncthreads();
    {
        float v = pf_r0(PB(1, 3), XX0(1, 3), XX1(1, 3), tid);
        mpo_full36(OFF_A, OFF_B, H0, tid);
        st_n13(H1, v, tid);
    }
    __syncthreads();
    {
        float v = pf_l0(PB(2, 0), XX0(2, 0), XX1(2, 0), tid);
        float ss = mpo_last36_sq(OFF_B, OFF_A, H1, tid);
        sumsq_publish(ss, tid);
        __syncthreads();
        float sc = read_scale();
        st_l0(H0, v, tid, sc);
    }
    __syncthreads();

    // ================= Row 2 L-part =================
    {
        pf_full(vf, PB(2, 1), XX0(2, 1), XX1(2, 1), tid);
        mpo_first36(OFF_A, OFF_B, H0, tid);
        st_full(H1, vf, tid);
    }
    __syncthreads();
    {
        float v = pf_slice36(PB(3, 0), XX0(3, 0), XX1(3, 0), 216, 36, tid); // (u,r)
        mpo_full36(OFF_B, OFF_A, H1, tid);      // L2 -> B (persists)
        st_id(H0, v, 36, tid);
    }
    __syncthreads();

    // ================= Row 3 (ping-pong in A; B holds L2) =================
    {
        float v = pf_d0(PB(3, 1), XX0(3, 1), XX1(3, 1), tid);   // [u][r][l]
        if (tid < 36) sm[P0 + tid] = sm[H0 + tid];
        st_id(H1, v, 216, tid);
    }
    __syncthreads();
    {
        float v = pf_d0(PB(3, 2), XX0(3, 2), XX1(3, 2), tid);
        rowstep(P1, P0, H1, 6, true, tid);
        st_id(H0, v, 216, tid);
    }
    __syncthreads();
    {
        float v = pf_slice36(PB(3, 3), XX0(3, 3), XX1(3, 3), 216, 1, tid);  // (u,l)
        rowstep(P0, P1, H0, 36, true, tid);
        st_id(H0 + 432, v, 36, tid);
    }
    __syncthreads();
    {
        float v = pf_r0(PB(2, 3), XX0(2, 3), XX1(2, 3), tid);   // identity [u][d][l]
        float ss = laststep_T_sq(H1, P0, H0 + 432, tid);
        sumsq_publish(ss, tid);
        __syncthreads();
        float sc = read_scale();
        st_n23(H0, v, tid, sc);
    }
    __syncthreads();

    // ================= R-part + merge =================
    rstep36(OFF_A, H1, H0, tid);
    __syncthreads();
    tgemm_tiled(H0, OFF_B, OFF_A, tid);
    __syncthreads();

    // ================= Final contraction with peps_center ================
    {
        const float xc0 = XX0(2, 2);
        const float xc1 = XX1(2, 2);
        float acc[10];
        #pragma unroll
        for (int o = 0; o < 10; o++) acc[o] = 0.0f;
        for (int k = tid; k < 1296; k += NT) {
            float e  = sm[H0 + k];
            float e0 = e * xc0;
            float e1 = e * xc1;
            #pragma unroll
            for (int o = 0; o < 10; o++)
                acc[o] += e0 * __ldg(pepsc + o * 1296 + k)
                        + e1 * __ldg(pepsc + 12960 + o * 1296 + k);
        }
        #pragma unroll
        for (int o = 0; o < 10; o++)
            #pragma unroll
            for (int off = 16; off > 0; off >>= 1)
                acc[o] += __shfl_down_sync(0xffffffffu, acc[o], off);
        const int w = tid >> 5;
        if ((tid & 31) == 0) {
            #pragma unroll
            for (int o = 0; o < 10; o++) sm[OFF_A + w * 10 + o] = acc[o];
        }
        __syncthreads();
        if (tid < 10) {
            float s = 0.0f;
            #pragma unroll
            for (int ww = 0; ww < 7; ww++) s += sm[OFF_A + ww * 10 + tid];
            sm[OFF_OUT + tid] = s;
        }
        __syncthreads();
    }

    if (tid < 10) {
        float nrm = 0.0f;
        #pragma unroll
        for (int o = 0; o < 10; o++) { float t = sm[OFF_OUT + o]; nrm += t * t; }
        out[b * 10 + tid] = sm[OFF_OUT + tid] * rsqrtf(nrm);
    }
}

// ---------------------------------------------------------------------------
// launch
// ---------------------------------------------------------------------------

extern "C" void kernel_launch(void* const* d_in, const int* in_sizes, int n_in,
                              void* d_out, int out_size)
{
    const float* inputs = (const float*)d_in[0];   // (B,4,4,2)
    const float* peps   = (const float*)d_in[1];   // (4,4,2,6,6,6,6)
    const float* pepsc  = (const float*)d_in[2];   // (2,10,6,6,6,6)
    float* out = (float*)d_out;                    // (B,10)

    const int B = in_sizes[0] / 32;

    cudaFuncSetAttribute(peps_forward_kernel,
                         cudaFuncAttributeMaxDynamicSharedMemorySize, SMEM_BYTES);
    peps_forward_kernel<<<B, NT, SMEM_BYTES>>>(inputs, peps, pepsc, out, B);
}

// round 8
// speedup vs baseline: 1.5903x; 1.5903x over previous
#include <cuda_runtime.h>

#define NT 224

// shared-memory layout (float offsets)
#define OFF_A    0        // 7776  MPO ping / row ping-pong / R / warp partials
#define OFF_B    7776     // 7776  MPO pong / env0 / env_top / L2
#define OFF_N    15552    // 2592  node double-buffer: H0, H1
#define OFF_RED  18144    // 8
#define OFF_OUT  18152    // 12
#define OFF_X    18164    // 32
#define SMEM_FLOATS 18208
#define SMEM_BYTES  (SMEM_FLOATS * 4)

#define H0 (OFF_N)
#define H1 (OFF_N + 1296)

extern __shared__ float sm[];

// ---------------------------------------------------------------------------
// sumsq all-reduce: every warp publishes its partial; all threads re-sum
// ---------------------------------------------------------------------------

__device__ __forceinline__ void sumsq_publish(float v, int tid)
{
    #pragma unroll
    for (int o = 16; o > 0; o >>= 1) v += __shfl_down_sync(0xffffffffu, v, o);
    if ((tid & 31) == 0) sm[OFF_RED + (tid >> 5)] = v;
}

__device__ __forceinline__ float read_scale()
{
    float s = 0.0f;
    #pragma unroll
    for (int w = 0; w < 7; w++) s += sm[OFF_RED + w];
    return rsqrtf(s);
}

// ---------------------------------------------------------------------------
// node prefetch (global -> regs) and commit (regs -> smem)
// node = x0 * P[slice] + x1 * P[1296 + slice]
// ---------------------------------------------------------------------------

__device__ __forceinline__ float pf_slice(const float* __restrict__ P,
                                          float x0, float x1,
                                          int cb, int cc,
                                          int sa, int sb, int sc,
                                          int n, int tid)
{
    if (tid >= n) return 0.0f;
    int a   = tid / (cb * cc);
    int rem = tid - a * (cb * cc);
    int bb  = rem / cc;
    int c   = rem - bb * cc;
    int addr = a * sa + bb * sb + c * sc;
    return x0 * __ldg(P + addr) + x1 * __ldg(P + addr + 1296);
}

__device__ __forceinline__ void st_slice(int off, float v, int n, int tid, float scale)
{
    if (tid < n) sm[off + tid] = v * scale;
}

// full node for mpo_full: buffer[(u*6+x)*36 + d*6 + r] from tensor [u][r][d][x]
__device__ __forceinline__ void pf_full(float* v, const float* __restrict__ P,
                                        float x0, float x1, int tid)
{
    #pragma unroll
    for (int i = 0; i < 6; i++) {
        int k = tid + i * NT;
        if (k < 1296) {
            int u = k / 216, rem = k % 216;
            int x = rem / 36; rem %= 36;
            int d = rem / 6, r = rem % 6;
            int addr = u * 216 + r * 36 + d * 6 + x;
            v[i] = x0 * __ldg(P + addr) + x1 * __ldg(P + addr + 1296);
        }
    }
}

__device__ __forceinline__ void st_full(int off, const float* v, int tid)
{
    #pragma unroll
    for (int i = 0; i < 6; i++) {
        int k = tid + i * NT;
        if (k < 1296) sm[off + k] = v[i];
    }
}

// ---------------------------------------------------------------------------
// small-row helpers (rows 0 and 3)
// ---------------------------------------------------------------------------

__device__ __forceinline__ void rowstep(int outOff, int inOff, int nodeOff,
                                        int As, bool swap, int tid)
{
    const int n = As * 36;
    for (int k = tid; k < n; k += NT) {
        int A = k / 36;
        int p = (k / 6) % 6;
        int q = k % 6;
        int nb = (swap ? (p * 6 + q) : (q * 6 + p)) * 6;
        const float2* ip = (const float2*)(sm + inOff + A * 6);
        float2 i01 = ip[0], i23 = ip[1], i45 = ip[2];
        float acc = i01.x * sm[nodeOff + nb + 0] + i01.y * sm[nodeOff + nb + 1]
                  + i23.x * sm[nodeOff + nb + 2] + i23.y * sm[nodeOff + nb + 3]
                  + i45.x * sm[nodeOff + nb + 4] + i45.y * sm[nodeOff + nb + 5];
        sm[outOff + k] = acc;
    }
}

__device__ __forceinline__ float laststep_sq(int outOff, int inOff, int nodeOff, int tid)
{
    float ss = 0.0f;
    for (int k = tid; k < 1296; k += NT) {
        int A = k / 6;
        int p = k % 6;
        const float2* ip = (const float2*)(sm + inOff + A * 6);
        float2 i01 = ip[0], i23 = ip[1], i45 = ip[2];
        const float* nb = sm + nodeOff + p * 6;
        float acc = i01.x * nb[0] + i01.y * nb[1]
                  + i23.x * nb[2] + i23.y * nb[3]
                  + i45.x * nb[4] + i45.y * nb[5];
        ss += acc * acc;
        sm[outOff + k] = acc;
    }
    return ss;
}

__device__ __forceinline__ float laststep_T_sq(int outOff, int inOff, int nodeOff, int tid)
{
    float ss = 0.0f;
    for (int k = tid; k < 1296; k += NT) {
        int A = k / 6;
        int p = k % 6;
        const float2* ip = (const float2*)(sm + inOff + A * 6);
        float2 i01 = ip[0], i23 = ip[1], i45 = ip[2];
        const float* nb = sm + nodeOff + p * 6;
        float acc = i01.x * nb[0] + i01.y * nb[1]
                  + i23.x * nb[2] + i23.y * nb[3]
                  + i45.x * nb[4] + i45.y * nb[5];
        ss += acc * acc;
        sm[outOff + p * 216 + (A / 6) * 6 + (A % 6)] = acc;
    }
    return ss;
}

// ---------------------------------------------------------------------------
// MPO kernels: 3(row) x 12(col) register tiles, 216 threads
// ---------------------------------------------------------------------------

__device__ __forceinline__ void mpo_first36(int outOff, int eOff, int nodeOff, int tid)
{
    if (tid >= 216) return;
    const int rg = tid / 3;
    const int cg = tid % 3;
    float acc[3][12];
    #pragma unroll
    for (int rr = 0; rr < 3; rr++)
        #pragma unroll
        for (int j = 0; j < 12; j++) acc[rr][j] = 0.0f;
    #pragma unroll 1
    for (int u = 0; u < 6; u++) {
        float e[3];
        #pragma unroll
        for (int rr = 0; rr < 3; rr++) e[rr] = sm[eOff + u * 216 + rg * 3 + rr];
        const float4* nb = (const float4*)(sm + nodeOff + u * 36 + cg * 12);
        float4 n0 = nb[0], n1 = nb[1], n2 = nb[2];
        #pragma unroll
        for (int rr = 0; rr < 3; rr++) {
            acc[rr][0] += e[rr] * n0.x; acc[rr][1]  += e[rr] * n0.y;
            acc[rr][2] += e[rr] * n0.z; acc[rr][3]  += e[rr] * n0.w;
            acc[rr][4] += e[rr] * n1.x; acc[rr][5]  += e[rr] * n1.y;
            acc[rr][6] += e[rr] * n1.z; acc[rr][7]  += e[rr] * n1.w;
            acc[rr][8] += e[rr] * n2.x; acc[rr][9]  += e[rr] * n2.y;
            acc[rr][10]+= e[rr] * n2.z; acc[rr][11] += e[rr] * n2.w;
        }
    }
    #pragma unroll
    for (int rr = 0; rr < 3; rr++) {
        float4* out = (float4*)(sm + outOff + (rg * 3 + rr) * 36 + cg * 12);
        out[0] = make_float4(acc[rr][0], acc[rr][1], acc[rr][2], acc[rr][3]);
        out[1] = make_float4(acc[rr][4], acc[rr][5], acc[rr][6], acc[rr][7]);
        out[2] = make_float4(acc[rr][8], acc[rr][9], acc[rr][10], acc[rr][11]);
    }
}

__device__ __forceinline__ void mpo_full36(int outOff, int inOff, int nodeOff, int tid)
{
    if (tid >= 216) return;
    const int rg = tid / 3;
    const int cg = tid % 3;
    float acc[3][12];
    #pragma unroll
    for (int rr = 0; rr < 3; rr++)
        #pragma unroll
        for (int j = 0; j < 12; j++) acc[rr][j] = 0.0f;
    #pragma unroll 1
    for (int u = 0; u < 6; u++) {
        float a[3][6];
        #pragma unroll
        for (int rr = 0; rr < 3; rr++) {
            const float2* sp = (const float2*)(sm + inOff + u * 1296 + (rg * 3 + rr) * 6);
            float2 s01 = sp[0], s23 = sp[1], s45 = sp[2];
            a[rr][0] = s01.x; a[rr][1] = s01.y;
            a[rr][2] = s23.x; a[rr][3] = s23.y;
            a[rr][4] = s45.x; a[rr][5] = s45.y;
        }
        #pragma unroll
        for (int x = 0; x < 6; x++) {
            const float4* nb = (const float4*)(sm + nodeOff + (u * 6 + x) * 36 + cg * 12);
            float4 n0 = nb[0], n1 = nb[1], n2 = nb[2];
            #pragma unroll
            for (int rr = 0; rr < 3; rr++) {
                float sv = a[rr][x];
                acc[rr][0] += sv * n0.x; acc[rr][1]  += sv * n0.y;
                acc[rr][2] += sv * n0.z; acc[rr][3]  += sv * n0.w;
                acc[rr][4] += sv * n1.x; acc[rr][5]  += sv * n1.y;
                acc[rr][6] += sv * n1.z; acc[rr][7]  += sv * n1.w;
                acc[rr][8] += sv * n2.x; acc[rr][9]  += sv * n2.y;
                acc[rr][10]+= sv * n2.z; acc[rr][11] += sv * n2.w;
            }
        }
    }
    #pragma unroll
    for (int rr = 0; rr < 3; rr++) {
        float4* out = (float4*)(sm + outOff + (rg * 3 + rr) * 36 + cg * 12);
        out[0] = make_float4(acc[rr][0], acc[rr][1], acc[rr][2], acc[rr][3]);
        out[1] = make_float4(acc[rr][4], acc[rr][5], acc[rr][6], acc[rr][7]);
        out[2] = make_float4(acc[rr][8], acc[rr][9], acc[rr][10], acc[rr][11]);
    }
}

__device__ __forceinline__ float mpo_last36_sq(int outOff, int inOff, int nodeOff, int tid)
{
    if (tid >= 216) return 0.0f;
    float acc[6] = {0, 0, 0, 0, 0, 0};
    #pragma unroll 1
    for (int u = 0; u < 6; u++) {
        const float2* sp = (const float2*)(sm + inOff + u * 1296 + tid * 6);
        float2 s01 = sp[0], s23 = sp[1], s45 = sp[2];
        float sx[6] = {s01.x, s01.y, s23.x, s23.y, s45.x, s45.y};
        #pragma unroll
        for (int x = 0; x < 6; x++) {
            float sv = sx[x];
            const float2* nb = (const float2*)(sm + nodeOff + (u * 6 + x) * 6);
            float2 n01 = nb[0], n23 = nb[1], n45 = nb[2];
            acc[0] += sv * n01.x; acc[1] += sv * n01.y;
            acc[2] += sv * n23.x; acc[3] += sv * n23.y;
            acc[4] += sv * n45.x; acc[5] += sv * n45.y;
        }
    }
    float2* out = (float2*)(sm + outOff + tid * 6);
    out[0] = make_float2(acc[0], acc[1]);
    out[1] = make_float2(acc[2], acc[3]);
    out[2] = make_float2(acc[4], acc[5]);
    float ss = 0.0f;
    #pragma unroll
    for (int i = 0; i < 6; i++) ss += acc[i] * acc[i];
    return ss;
}

__device__ __noinline__ void rstep36(int outOff, int ebOff, int nodeOff, int tid)
{
    if (tid >= 216) return;
    int u3 = tid / 36;
    int dd = tid % 36;
    float acc[36];
    #pragma unroll
    for (int i = 0; i < 36; i++) acc[i] = 0.0f;
    #pragma unroll 1
    for (int d3 = 0; d3 < 6; d3++) {
        const float2* ep = (const float2*)(sm + ebOff + d3 * 216 + dd * 6);
        float2 e01 = ep[0], e23 = ep[1], e45 = ep[2];
        float eb[6] = {e01.x, e01.y, e23.x, e23.y, e45.x, e45.y};
        const float2* np = (const float2*)(sm + nodeOff + u3 * 36 + d3 * 6);
        float2 n01 = np[0], n23v = np[1], n45 = np[2];
        float nv[6] = {n01.x, n01.y, n23v.x, n23v.y, n45.x, n45.y};
        #pragma unroll
        for (int d2 = 0; d2 < 6; d2++)
            #pragma unroll
            for (int l3 = 0; l3 < 6; l3++)
                acc[d2 * 6 + l3] += eb[d2] * nv[l3];
    }
    float4* out = (float4*)(sm + outOff + tid * 36);
    #pragma unroll
    for (int q = 0; q < 9; q++)
        out[q] = make_float4(acc[q*4], acc[q*4+1], acc[q*4+2], acc[q*4+3]);
}

__device__ __noinline__ void tgemm_tiled(int tOff, int lOff, int rOff, int tid)
{
    if (tid >= 162) return;
    int pr = tid / 9;
    int bt = tid % 9;
    int u  = pr / 3;
    int l0 = (pr % 3) * 2;
    int b0 = bt * 4;
    float acc[8];
    #pragma unroll
    for (int i = 0; i < 8; i++) acc[i] = 0.0f;
    const float* Lp = sm + lOff + u * 1296 + l0;
    const float* Rp = sm + rOff + b0;
    #pragma unroll 4
    for (int m = 0; m < 216; m++) {
        float2 a  = *(const float2*)(Lp + m * 6);
        float4 bv = *(const float4*)(Rp + m * 36);
        acc[0] += a.x * bv.x; acc[1] += a.x * bv.y;
        acc[2] += a.x * bv.z; acc[3] += a.x * bv.w;
        acc[4] += a.y * bv.x; acc[5] += a.y * bv.y;
        acc[6] += a.y * bv.z; acc[7] += a.y * bv.w;
    }
    #pragma unroll
    for (int j = 0; j < 4; j++) {
        int beta = b0 + j;
        int d = beta / 6;
        int r = beta % 6;
        sm[tOff + u * 216 + r * 36 + d * 6 + l0]     = acc[j];
        sm[tOff + u * 216 + r * 36 + d * 6 + l0 + 1] = acc[4 + j];
    }
}

// ---------------------------------------------------------------------------
// kernel: one block per batch element, software-pipelined node loads
// ---------------------------------------------------------------------------

__global__ __launch_bounds__(NT, 3)
void peps_forward_kernel(const float* __restrict__ inputs,
                         const float* __restrict__ peps,
                         const float* __restrict__ pepsc,
                         float* __restrict__ out, int B)
{
    const int tid = threadIdx.x;
    const int b = blockIdx.x;

    if (tid < 32) sm[OFF_X + tid] = inputs[b * 32 + tid];
    __syncthreads();

    #define PB(i, j)  (peps + ((i) * 4 + (j)) * 2 * 1296)
    #define XX0(i, j) sm[OFF_X + ((i) * 4 + (j)) * 2]
    #define XX1(i, j) sm[OFF_X + ((i) * 4 + (j)) * 2 + 1]

    const int P0 = OFF_A;
    const int P1 = OFF_A + 1296;
    float vf[6];

    // ---- init: n00 [r][d] -> H0 ----
    {
        float v = pf_slice(PB(0, 0), XX0(0, 0), XX1(0, 0), 6, 1, 36, 6, 0, 36, tid);
        st_slice(H0, v, 36, tid, 1.0f);
    }
    __syncthreads();

    // ================= Row 0 =================
    {
        float v = pf_slice(PB(0, 1), XX0(0, 1), XX1(0, 1), 6, 6, 36, 6, 1, 216, tid);
        if (tid < 36) { int d0 = tid / 6, r = tid % 6; sm[P0 + tid] = sm[H0 + r * 6 + d0]; }
        st_slice(H1, v, 216, tid, 1.0f);
    }
    __syncthreads();
    {
        float v = pf_slice(PB(0, 2), XX0(0, 2), XX1(0, 2), 6, 6, 36, 6, 1, 216, tid);
        rowstep(P1, P0, H1, 6, false, tid);
        st_slice(H0, v, 216, tid, 1.0f);
    }
    __syncthreads();
    {
        float v = pf_slice(PB(0, 3), XX0(0, 3), XX1(0, 3), 6, 1, 6, 1, 0, 36, tid);
        rowstep(P0, P1, H0, 36, false, tid);
        st_slice(H1, v, 36, tid, 1.0f);
    }
    __syncthreads();
    {
        float v = pf_slice(PB(1, 0), XX0(1, 0), XX1(1, 0), 6, 6, 216, 6, 36, 216, tid);
        float ss = laststep_sq(OFF_B, P0, H1, tid);
        sumsq_publish(ss, tid);
        __syncthreads();
        float sc = read_scale();
        st_slice(H0, v, 216, tid, sc);
    }
    __syncthreads();

    // ================= Row 1 =================
    {
        pf_full(vf, PB(1, 1), XX0(1, 1), XX1(1, 1), tid);
        mpo_first36(OFF_A, OFF_B, H0, tid);
        st_full(H1, vf, tid);
    }
    __syncthreads();
    {
        pf_full(vf, PB(1, 2), XX0(1, 2), XX1(1, 2), tid);
        mpo_full36(OFF_B, OFF_A, H1, tid);
        st_full(H0, vf, tid);
    }
    __syncthreads();
    {
        float v = pf_slice(PB(1, 3), XX0(1, 3), XX1(1, 3), 6, 6, 216, 1, 6, 216, tid); // [u][x][d]
        mpo_full36(OFF_A, OFF_B, H0, tid);
        st_slice(H1, v, 216, tid, 1.0f);
    }
    __syncthreads();
    {
        float v = pf_slice(PB(2, 0), XX0(2, 0), XX1(2, 0), 6, 6, 216, 6, 36, 216, tid);
        float ss = mpo_last36_sq(OFF_B, OFF_A, H1, tid);
        sumsq_publish(ss, tid);
        __syncthreads();
        float sc = read_scale();
        st_slice(H0, v, 216, tid, sc);
    }
    __syncthreads();

    // ================= Row 2 L-part =================
    {
        pf_full(vf, PB(2, 1), XX0(2, 1), XX1(2, 1), tid);
        mpo_first36(OFF_A, OFF_B, H0, tid);
        st_full(H1, vf, tid);
    }
    __syncthreads();
    {
        float v = pf_slice(PB(3, 0), XX0(3, 0), XX1(3, 0), 6, 1, 216, 36, 0, 36, tid); // [u][r]
        mpo_full36(OFF_B, OFF_A, H1, tid);   // L2 -> B (persists)
        st_slice(H0, v, 36, tid, 1.0f);
    }
    __syncthreads();

    // ================= Row 3 (ping-pong in A; B holds L2) =================
    {
        float v = pf_slice(PB(3, 1), XX0(3, 1), XX1(3, 1), 6, 6, 216, 36, 1, 216, tid); // [u][r][x]
        if (tid < 36) sm[P0 + tid] = sm[H0 + tid];
        st_slice(H1, v, 216, tid, 1.0f);
    }
    __syncthreads();
    {
        float v = pf_slice(PB(3, 2), XX0(3, 2), XX1(3, 2), 6, 6, 216, 36, 1, 216, tid);
        rowstep(P1, P0, H1, 6, true, tid);
        st_slice(H0, v, 216, tid, 1.0f);
    }
    __syncthreads();
    {
        float v = pf_slice(PB(3, 3), XX0(3, 3), XX1(3, 3), 6, 1, 216, 1, 0, 36, tid);   // [u][x]
        rowstep(P0, P1, H0, 36, true, tid);
        st_slice(H0 + 432, v, 36, tid, 1.0f);   // n33 parked past n32
    }
    __syncthreads();
    {
        float v = pf_slice(PB(2, 3), XX0(2, 3), XX1(2, 3), 6, 6, 216, 6, 1, 216, tid);
        float ss = laststep_T_sq(H1, P0, H0 + 432, tid);
        sumsq_publish(ss, tid);
        __syncthreads();
        float sc = read_scale();
        st_slice(H0, v, 216, tid, sc);
    }
    __syncthreads();

    // ================= R-part + merge =================
    rstep36(OFF_A, H1, H0, tid);          // R -> A
    __syncthreads();
    tgemm_tiled(H0, OFF_B, OFF_A, tid);   // T -> H0
    __syncthreads();

    // ================= Final contraction with peps_center (float4) ========
    {
        const float xc0 = XX0(2, 2);
        const float xc1 = XX1(2, 2);
        float acc[10];
        #pragma unroll
        for (int o = 0; o < 10; o++) acc[o] = 0.0f;
        // 1296 = 324 float4; threads 0..NT-1 cover kk = tid*4, stride NT*4
        for (int kk = tid * 4; kk < 1296; kk += NT * 4) {
            const float4 e4 = *(const float4*)(sm + H0 + kk);
            float4 e0 = make_float4(e4.x * xc0, e4.y * xc0, e4.z * xc0, e4.w * xc0);
            float4 e1 = make_float4(e4.x * xc1, e4.y * xc1, e4.z * xc1, e4.w * xc1);
            #pragma unroll
            for (int o = 0; o < 10; o++) {
                float4 p0 = __ldg((const float4*)(pepsc + o * 1296 + kk));
                float4 p1 = __ldg((const float4*)(pepsc + 12960 + o * 1296 + kk));
                acc[o] += e0.x * p0.x + e0.y * p0.y + e0.z * p0.z + e0.w * p0.w
                        + e1.x * p1.x + e1.y * p1.y + e1.z * p1.z + e1.w * p1.w;
            }
        }
        #pragma unroll
        for (int o = 0; o < 10; o++)
            #pragma unroll
            for (int off = 16; off > 0; off >>= 1)
                acc[o] += __shfl_down_sync(0xffffffffu, acc[o], off);
        const int w = tid >> 5;
        if ((tid & 31) == 0) {
            #pragma unroll
            for (int o = 0; o < 10; o++) sm[OFF_A + w * 10 + o] = acc[o];
        }
        __syncthreads();
        if (tid < 10) {
            float s = 0.0f;
            #pragma unroll
            for (int ww = 0; ww < 7; ww++) s += sm[OFF_A + ww * 10 + tid];
            sm[OFF_OUT + tid] = s;
        }
        __syncthreads();
    }

    if (tid < 10) {
        float nrm = 0.0f;
        #pragma unroll
        for (int o = 0; o < 10; o++) { float t = sm[OFF_OUT + o]; nrm += t * t; }
        out[b * 10 + tid] = sm[OFF_OUT + tid] * rsqrtf(nrm);
    }
}

// ---------------------------------------------------------------------------
// launch
// ---------------------------------------------------------------------------

extern "C" void kernel_launch(void* const* d_in, const int* in_sizes, int n_in,
                              void* d_out, int out_size)
{
    const float* inputs = (const float*)d_in[0];   // (B,4,4,2)
    const float* peps   = (const float*)d_in[1];   // (4,4,2,6,6,6,6)
    const float* pepsc  = (const float*)d_in[2];   // (2,10,6,6,6,6)
    float* out = (float*)d_out;                    // (B,10)

    const int B = in_sizes[0] / 32;

    cudaFuncSetAttribute(peps_forward_kernel,
                         cudaFuncAttributeMaxDynamicSharedMemorySize, SMEM_BYTES);
    peps_forward_kernel<<<B, NT, SMEM_BYTES>>>(inputs, peps, pepsc, out, B);
}

// round 10
// speedup vs baseline: 1.6205x; 1.0190x over previous
#include <cuda_runtime.h>

#define NT 224

// shared-memory layout (float offsets)
#define OFF_A    0        // 7776  MPO ping / row ping-pong / R / warp partials
#define OFF_B    7776     // 7776  MPO pong / env0 / env_top / L2
#define OFF_N    15552    // 2592  node double-buffer: H0, H1
#define OFF_RED  18144    // 8
#define OFF_OUT  18152    // 12
#define OFF_X    18164    // 32
#define SMEM_FLOATS 18208
#define SMEM_BYTES  (SMEM_FLOATS * 4)

#define H0 (OFF_N)
#define H1 (OFF_N + 1296)

extern __shared__ float sm[];

// ---------------------------------------------------------------------------
// sumsq all-reduce
// ---------------------------------------------------------------------------

__device__ __forceinline__ void sumsq_publish(float v, int tid)
{
    #pragma unroll
    for (int o = 16; o > 0; o >>= 1) v += __shfl_down_sync(0xffffffffu, v, o);
    if ((tid & 31) == 0) sm[OFF_RED + (tid >> 5)] = v;
}

__device__ __forceinline__ float read_scale()
{
    float s = 0.0f;
    #pragma unroll
    for (int w = 0; w < 7; w++) s += sm[OFF_RED + w];
    return rsqrtf(s);
}

// ---------------------------------------------------------------------------
// node prefetch: COALESCED global reads (source-linear), permuted smem stores
// node = x0 * P[addr] + x1 * P[addr + 1296];  source tensor layout [u][r][d][l]
// ---------------------------------------------------------------------------

// -- full node (n11, n12, n21): read linear k, store [u][l][d][r] --
__device__ __forceinline__ void pf_full(float* v, const float* __restrict__ P,
                                        float x0, float x1, int tid)
{
    #pragma unroll
    for (int i = 0; i < 6; i++) {
        int k = tid + i * NT;
        if (k < 1296) v[i] = x0 * __ldg(P + k) + x1 * __ldg(P + k + 1296);
    }
}

__device__ __forceinline__ void st_full(int off, const float* v, int tid)
{
    #pragma unroll
    for (int i = 0; i < 6; i++) {
        int k = tid + i * NT;
        if (k < 1296) {
            int u = k / 216, rem = k % 216;
            int r = rem / 36;
            int d = (rem / 6) % 6;
            int l = rem % 6;
            sm[off + u * 216 + l * 36 + d * 6 + r] = v[i];
        }
    }
}

// -- n10 / n20 (slice l=0): enumerate (u,r,d) source order; store [u][d][r] --
__device__ __forceinline__ float pf_l0(const float* __restrict__ P,
                                       float x0, float x1, int tid)
{
    if (tid >= 216) return 0.0f;
    int u = tid / 36, r = (tid / 6) % 6, d = tid % 6;
    int addr = u * 216 + r * 36 + d * 6;
    return x0 * __ldg(P + addr) + x1 * __ldg(P + addr + 1296);
}

__device__ __forceinline__ void st_l0(int off, float v, int tid, float scale)
{
    if (tid < 216) {
        int u = tid / 36, r = (tid / 6) % 6, d = tid % 6;
        sm[off + u * 36 + d * 6 + r] = v * scale;
    }
}

// -- n13 (slice r=0): contiguous per-u source reads; store [u][l][d] --
__device__ __forceinline__ float pf_r0(const float* __restrict__ P,
                                       float x0, float x1, int tid)
{
    if (tid >= 216) return 0.0f;
    int u = tid / 36, rest = tid % 36;        // rest = d*6 + l
    int addr = u * 216 + rest;
    return x0 * __ldg(P + addr) + x1 * __ldg(P + addr + 1296);
}

__device__ __forceinline__ void st_n13(int off, float v, int tid)
{
    if (tid < 216) {
        int u = tid / 36, rest = tid % 36;
        int d = rest / 6, l = rest % 6;
        sm[off + u * 36 + l * 6 + d] = v;
    }
}

// -- n23 (slice r=0): identity on (d,l); store [u][d][l] --
__device__ __forceinline__ void st_n23(int off, float v, int tid, float scale)
{
    if (tid < 216) sm[off + tid] = v * scale;   // tid = u*36 + d*6 + l
}

// -- n01/n02 (slice u=0): identity, contiguous --
__device__ __forceinline__ float pf_u0(const float* __restrict__ P,
                                       float x0, float x1, int tid)
{
    if (tid >= 216) return 0.0f;
    return x0 * __ldg(P + tid) + x1 * __ldg(P + tid + 1296);
}

__device__ __forceinline__ void st_id(int off, float v, int n, int tid)
{
    if (tid < n) sm[off + tid] = v;
}

// -- small 36-elem slices --
__device__ __forceinline__ float pf_slice36(const float* __restrict__ P,
                                            float x0, float x1,
                                            int sa, int sb, int tid)
{
    if (tid >= 36) return 0.0f;
    int a = tid / 6, bb = tid % 6;
    int addr = a * sa + bb * sb;
    return x0 * __ldg(P + addr) + x1 * __ldg(P + addr + 1296);
}

// -- n31/n32 (slice d=0): runs of 6, identity layout [u][r][l] --
__device__ __forceinline__ float pf_d0(const float* __restrict__ P,
                                       float x0, float x1, int tid)
{
    if (tid >= 216) return 0.0f;
    int u = tid / 36, r = (tid / 6) % 6, l = tid % 6;
    int addr = u * 216 + r * 36 + l;
    return x0 * __ldg(P + addr) + x1 * __ldg(P + addr + 1296);
}

// ---------------------------------------------------------------------------
// small-row helpers (rows 0 and 3)
// ---------------------------------------------------------------------------

__device__ __forceinline__ void rowstep(int outOff, int inOff, int nodeOff,
                                        int As, bool swap, int tid)
{
    const int n = As * 36;
    for (int k = tid; k < n; k += NT) {
        int A = k / 36;
        int p = (k / 6) % 6;
        int q = k % 6;
        int nb = (swap ? (p * 6 + q) : (q * 6 + p)) * 6;
        const float2* ip = (const float2*)(sm + inOff + A * 6);
        float2 i01 = ip[0], i23 = ip[1], i45 = ip[2];
        float acc = i01.x * sm[nodeOff + nb + 0] + i01.y * sm[nodeOff + nb + 1]
                  + i23.x * sm[nodeOff + nb + 2] + i23.y * sm[nodeOff + nb + 3]
                  + i45.x * sm[nodeOff + nb + 4] + i45.y * sm[nodeOff + nb + 5];
        sm[outOff + k] = acc;
    }
}

__device__ __forceinline__ float laststep_sq(int outOff, int inOff, int nodeOff, int tid)
{
    float ss = 0.0f;
    for (int k = tid; k < 1296; k += NT) {
        int A = k / 6;
        int p = k % 6;
        const float2* ip = (const float2*)(sm + inOff + A * 6);
        float2 i01 = ip[0], i23 = ip[1], i45 = ip[2];
        const float* nb = sm + nodeOff + p * 6;
        float acc = i01.x * nb[0] + i01.y * nb[1]
                  + i23.x * nb[2] + i23.y * nb[3]
                  + i45.x * nb[4] + i45.y * nb[5];
        ss += acc * acc;
        sm[outOff + k] = acc;
    }
    return ss;
}

__device__ __forceinline__ float laststep_T_sq(int outOff, int inOff, int nodeOff, int tid)
{
    float ss = 0.0f;
    for (int k = tid; k < 1296; k += NT) {
        int A = k / 6;
        int p = k % 6;
        const float2* ip = (const float2*)(sm + inOff + A * 6);
        float2 i01 = ip[0], i23 = ip[1], i45 = ip[2];
        const float* nb = sm + nodeOff + p * 6;
        float acc = i01.x * nb[0] + i01.y * nb[1]
                  + i23.x * nb[2] + i23.y * nb[3]
                  + i45.x * nb[4] + i45.y * nb[5];
        ss += acc * acc;
        sm[outOff + p * 216 + (A / 6) * 6 + (A % 6)] = acc;
    }
    return ss;
}

// ---------------------------------------------------------------------------
// MPO kernels: 3(row) x 12(col) register tiles, 216 threads
// ---------------------------------------------------------------------------

__device__ __forceinline__ void mpo_first36(int outOff, int eOff, int nodeOff, int tid)
{
    if (tid >= 216) return;
    const int rg = tid / 3;
    const int cg = tid % 3;
    float acc[3][12];
    #pragma unroll
    for (int rr = 0; rr < 3; rr++)
        #pragma unroll
        for (int j = 0; j < 12; j++) acc[rr][j] = 0.0f;
    #pragma unroll 1
    for (int u = 0; u < 6; u++) {
        float e[3];
        #pragma unroll
        for (int rr = 0; rr < 3; rr++) e[rr] = sm[eOff + u * 216 + rg * 3 + rr];
        const float4* nb = (const float4*)(sm + nodeOff + u * 36 + cg * 12);
        float4 n0 = nb[0], n1 = nb[1], n2 = nb[2];
        #pragma unroll
        for (int rr = 0; rr < 3; rr++) {
            acc[rr][0] += e[rr] * n0.x; acc[rr][1]  += e[rr] * n0.y;
            acc[rr][2] += e[rr] * n0.z; acc[rr][3]  += e[rr] * n0.w;
            acc[rr][4] += e[rr] * n1.x; acc[rr][5]  += e[rr] * n1.y;
            acc[rr][6] += e[rr] * n1.z; acc[rr][7]  += e[rr] * n1.w;
            acc[rr][8] += e[rr] * n2.x; acc[rr][9]  += e[rr] * n2.y;
            acc[rr][10]+= e[rr] * n2.z; acc[rr][11] += e[rr] * n2.w;
        }
    }
    #pragma unroll
    for (int rr = 0; rr < 3; rr++) {
        float4* out = (float4*)(sm + outOff + (rg * 3 + rr) * 36 + cg * 12);
        out[0] = make_float4(acc[rr][0], acc[rr][1], acc[rr][2], acc[rr][3]);
        out[1] = make_float4(acc[rr][4], acc[rr][5], acc[rr][6], acc[rr][7]);
        out[2] = make_float4(acc[rr][8], acc[rr][9], acc[rr][10], acc[rr][11]);
    }
}

__device__ __forceinline__ void mpo_full36(int outOff, int inOff, int nodeOff, int tid)
{
    if (tid >= 216) return;
    const int rg = tid / 3;
    const int cg = tid % 3;
    float acc[3][12];
    #pragma unroll
    for (int rr = 0; rr < 3; rr++)
        #pragma unroll
        for (int j = 0; j < 12; j++) acc[rr][j] = 0.0f;
    #pragma unroll 1
    for (int u = 0; u < 6; u++) {
        float a[3][6];
        #pragma unroll
        for (int rr = 0; rr < 3; rr++) {
            const float2* sp = (const float2*)(sm + inOff + u * 1296 + (rg * 3 + rr) * 6);
            float2 s01 = sp[0], s23 = sp[1], s45 = sp[2];
            a[rr][0] = s01.x; a[rr][1] = s01.y;
            a[rr][2] = s23.x; a[rr][3] = s23.y;
            a[rr][4] = s45.x; a[rr][5] = s45.y;
        }
        #pragma unroll
        for (int x = 0; x < 6; x++) {
            const float4* nb = (const float4*)(sm + nodeOff + (u * 6 + x) * 36 + cg * 12);
            float4 n0 = nb[0], n1 = nb[1], n2 = nb[2];
            #pragma unroll
            for (int rr = 0; rr < 3; rr++) {
                float sv = a[rr][x];
                acc[rr][0] += sv * n0.x; acc[rr][1]  += sv * n0.y;
                acc[rr][2] += sv * n0.z; acc[rr][3]  += sv * n0.w;
                acc[rr][4] += sv * n1.x; acc[rr][5]  += sv * n1.y;
                acc[rr][6] += sv * n1.z; acc[rr][7]  += sv * n1.w;
                acc[rr][8] += sv * n2.x; acc[rr][9]  += sv * n2.y;
                acc[rr][10]+= sv * n2.z; acc[rr][11] += sv * n2.w;
            }
        }
    }
    #pragma unroll
    for (int rr = 0; rr < 3; rr++) {
        float4* out = (float4*)(sm + outOff + (rg * 3 + rr) * 36 + cg * 12);
        out[0] = make_float4(acc[rr][0], acc[rr][1], acc[rr][2], acc[rr][3]);
        out[1] = make_float4(acc[rr][4], acc[rr][5], acc[rr][6], acc[rr][7]);
        out[2] = make_float4(acc[rr][8], acc[rr][9], acc[rr][10], acc[rr][11]);
    }
}

__device__ __forceinline__ float mpo_last36_sq(int outOff, int inOff, int nodeOff, int tid)
{
    if (tid >= 216) return 0.0f;
    float acc[6] = {0, 0, 0, 0, 0, 0};
    #pragma unroll 1
    for (int u = 0; u < 6; u++) {
        const float2* sp = (const float2*)(sm + inOff + u * 1296 + tid * 6);
        float2 s01 = sp[0], s23 = sp[1], s45 = sp[2];
        float sx[6] = {s01.x, s01.y, s23.x, s23.y, s45.x, s45.y};
        #pragma unroll
        for (int x = 0; x < 6; x++) {
            float sv = sx[x];
            const float2* nb = (const float2*)(sm + nodeOff + (u * 6 + x) * 6);
            float2 n01 = nb[0], n23 = nb[1], n45 = nb[2];
            acc[0] += sv * n01.x; acc[1] += sv * n01.y;
            acc[2] += sv * n23.x; acc[3] += sv * n23.y;
            acc[4] += sv * n45.x; acc[5] += sv * n45.y;
        }
    }
    float2* out = (float2*)(sm + outOff + tid * 6);
    out[0] = make_float2(acc[0], acc[1]);
    out[1] = make_float2(acc[2], acc[3]);
    out[2] = make_float2(acc[4], acc[5]);
    float ss = 0.0f;
    #pragma unroll
    for (int i = 0; i < 6; i++) ss += acc[i] * acc[i];
    return ss;
}

__device__ __noinline__ void rstep36(int outOff, int ebOff, int nodeOff, int tid)
{
    if (tid >= 216) return;
    int u3 = tid / 36;
    int dd = tid % 36;
    float acc[36];
    #pragma unroll
    for (int i = 0; i < 36; i++) acc[i] = 0.0f;
    #pragma unroll 1
    for (int d3 = 0; d3 < 6; d3++) {
        const float2* ep = (const float2*)(sm + ebOff + d3 * 216 + dd * 6);
        float2 e01 = ep[0], e23 = ep[1], e45 = ep[2];
        float eb[6] = {e01.x, e01.y, e23.x, e23.y, e45.x, e45.y};
        const float2* np = (const float2*)(sm + nodeOff + u3 * 36 + d3 * 6);
        float2 n01 = np[0], n23v = np[1], n45 = np[2];
        float nv[6] = {n01.x, n01.y, n23v.x, n23v.y, n45.x, n45.y};
        #pragma unroll
        for (int d2 = 0; d2 < 6; d2++)
            #pragma unroll
            for (int l3 = 0; l3 < 6; l3++)
                acc[d2 * 6 + l3] += eb[d2] * nv[l3];
    }
    float4* out = (float4*)(sm + outOff + tid * 36);
    #pragma unroll
    for (int q = 0; q < 9; q++)
        out[q] = make_float4(acc[q*4], acc[q*4+1], acc[q*4+2], acc[q*4+3]);
}

__device__ __noinline__ void tgemm_tiled(int tOff, int lOff, int rOff, int tid)
{
    if (tid >= 162) return;
    int pr = tid / 9;
    int bt = tid % 9;
    int u  = pr / 3;
    int l0 = (pr % 3) * 2;
    int b0 = bt * 4;
    float acc[8];
    #pragma unroll
    for (int i = 0; i < 8; i++) acc[i] = 0.0f;
    const float* Lp = sm + lOff + u * 1296 + l0;
    const float* Rp = sm + rOff + b0;
    #pragma unroll 4
    for (int m = 0; m < 216; m++) {
        float2 a  = *(const float2*)(Lp + m * 6);
        float4 bv = *(const float4*)(Rp + m * 36);
        acc[0] += a.x * bv.x; acc[1] += a.x * bv.y;
        acc[2] += a.x * bv.z; acc[3] += a.x * bv.w;
        acc[4] += a.y * bv.x; acc[5] += a.y * bv.y;
        acc[6] += a.y * bv.z; acc[7] += a.y * bv.w;
    }
    #pragma unroll
    for (int j = 0; j < 4; j++) {
        int beta = b0 + j;
        int d = beta / 6;
        int r = beta % 6;
        sm[tOff + u * 216 + r * 36 + d * 6 + l0]     = acc[j];
        sm[tOff + u * 216 + r * 36 + d * 6 + l0 + 1] = acc[4 + j];
    }
}

// ---------------------------------------------------------------------------
// kernel
// ---------------------------------------------------------------------------

__global__ __launch_bounds__(NT, 3)
void peps_forward_kernel(const float* __restrict__ inputs,
                         const float* __restrict__ peps,
                         const float* __restrict__ pepsc,
                         float* __restrict__ out, int B)
{
    const int tid = threadIdx.x;
    const int b = blockIdx.x;

    if (tid < 32) sm[OFF_X + tid] = inputs[b * 32 + tid];
    __syncthreads();

    #define PB(i, j)  (peps + ((i) * 4 + (j)) * 2 * 1296)
    #define XX0(i, j) sm[OFF_X + ((i) * 4 + (j)) * 2]
    #define XX1(i, j) sm[OFF_X + ((i) * 4 + (j)) * 2 + 1]

    const int P0 = OFF_A;
    const int P1 = OFF_A + 1296;
    float vf[6];

    // ---- init: n00 (u=0,l=0, transposed into P0) + n01 -> H1 ----
    {
        float v00 = pf_slice36(PB(0, 0), XX0(0, 0), XX1(0, 0), 36, 6, tid); // (r,d)
        float v01 = pf_u0(PB(0, 1), XX0(0, 1), XX1(0, 1), tid);
        if (tid < 36) sm[P0 + (tid % 6) * 6 + (tid / 6)] = v00;  // P0[d*6+r]
        st_id(H1, v01, 216, tid);
    }
    __syncthreads();
    // step: rowstep with n01; prefetch n02
    {
        float v = pf_u0(PB(0, 2), XX0(0, 2), XX1(0, 2), tid);
        rowstep(P1, P0, H1, 6, false, tid);
        st_id(H0, v, 216, tid);
    }
    __syncthreads();
    // step: rowstep with n02; prefetch n03 (u=0,r=0 -> (d,l) identity)
    {
        float v = pf_slice36(PB(0, 3), XX0(0, 3), XX1(0, 3), 6, 1, tid);
        rowstep(P0, P1, H0, 36, false, tid);
        st_id(H1, v, 36, tid);
    }
    __syncthreads();
    // step: env0 raw -> B ; scale into n10 [u][d][r]
    {
        float v = pf_l0(PB(1, 0), XX0(1, 0), XX1(1, 0), tid);
        float ss = laststep_sq(OFF_B, P0, H1, tid);
        sumsq_publish(ss, tid);
        __syncthreads();
        float sc = read_scale();
        st_l0(H0, v, tid, sc);
    }
    __syncthreads();

    // ================= Row 1 =================
    {
        pf_full(vf, PB(1, 1), XX0(1, 1), XX1(1, 1), tid);
        mpo_first36(OFF_A, OFF_B, H0, tid);
        st_full(H1, vf, tid);
    }
    __syncthreads();
    {
        pf_full(vf, PB(1, 2), XX0(1, 2), XX1(1, 2), tid);
        mpo_full36(OFF_B, OFF_A, H1, tid);
        st_full(H0, vf, tid);
    }
    __syncthreads();
    {
        float v = pf_r0(PB(1, 3), XX0(1, 3), XX1(1, 3), tid);
        mpo_full36(OFF_A, OFF_B, H0, tid);
        st_n13(H1, v, tid);
    }
    __syncthreads();
    {
        float v = pf_l0(PB(2, 0), XX0(2, 0), XX1(2, 0), tid);
        float ss = mpo_last36_sq(OFF_B, OFF_A, H1, tid);
        sumsq_publish(ss, tid);
        __syncthreads();
        float sc = read_scale();
        st_l0(H0, v, tid, sc);
    }
    __syncthreads();

    // ================= Row 2 L-part =================
    {
        pf_full(vf, PB(2, 1), XX0(2, 1), XX1(2, 1), tid);
        mpo_first36(OFF_A, OFF_B, H0, tid);
        st_full(H1, vf, tid);
    }
    __syncthreads();
    {
        float v = pf_slice36(PB(3, 0), XX0(3, 0), XX1(3, 0), 216, 36, tid); // (u,r)
        mpo_full36(OFF_B, OFF_A, H1, tid);      // L2 -> B (persists)
        st_id(H0, v, 36, tid);
    }
    __syncthreads();

    // ================= Row 3 (ping-pong in A; B holds L2) =================
    {
        float v = pf_d0(PB(3, 1), XX0(3, 1), XX1(3, 1), tid);   // [u][r][l]
        if (tid < 36) sm[P0 + tid] = sm[H0 + tid];
        st_id(H1, v, 216, tid);
    }
    __syncthreads();
    {
        float v = pf_d0(PB(3, 2), XX0(3, 2), XX1(3, 2), tid);
        rowstep(P1, P0, H1, 6, true, tid);
        st_id(H0, v, 216, tid);
    }
    __syncthreads();
    {
        float v = pf_slice36(PB(3, 3), XX0(3, 3), XX1(3, 3), 216, 1, tid);  // (u,l)
        rowstep(P0, P1, H0, 36, true, tid);
        st_id(H0 + 432, v, 36, tid);
    }
    __syncthreads();
    {
        float v = pf_r0(PB(2, 3), XX0(2, 3), XX1(2, 3), tid);   // identity [u][d][l]
        float ss = laststep_T_sq(H1, P0, H0 + 432, tid);
        sumsq_publish(ss, tid);
        __syncthreads();
        float sc = read_scale();
        st_n23(H0, v, tid, sc);
    }
    __syncthreads();

    // ================= R-part + merge =================
    rstep36(OFF_A, H1, H0, tid);
    __syncthreads();
    tgemm_tiled(H0, OFF_B, OFF_A, tid);
    __syncthreads();

    // ================= Final contraction with peps_center (float4) ========
    {
        const float xc0 = XX0(2, 2);
        const float xc1 = XX1(2, 2);
        float acc[10];
        #pragma unroll
        for (int o = 0; o < 10; o++) acc[o] = 0.0f;
        for (int kk = tid * 4; kk < 1296; kk += NT * 4) {
            const float4 e4 = *(const float4*)(sm + H0 + kk);
            float4 e0 = make_float4(e4.x * xc0, e4.y * xc0, e4.z * xc0, e4.w * xc0);
            float4 e1 = make_float4(e4.x * xc1, e4.y * xc1, e4.z * xc1, e4.w * xc1);
            #pragma unroll
            for (int o = 0; o < 10; o++) {
                float4 p0 = __ldg((const float4*)(pepsc + o * 1296 + kk));
                float4 p1 = __ldg((const float4*)(pepsc + 12960 + o * 1296 + kk));
                acc[o] += e0.x * p0.x + e0.y * p0.y + e0.z * p0.z + e0.w * p0.w
                        + e1.x * p1.x + e1.y * p1.y + e1.z * p1.z + e1.w * p1.w;
            }
        }
        #pragma unroll
        for (int o = 0; o < 10; o++)
            #pragma unroll
            for (int off = 16; off > 0; off >>= 1)
                acc[o] += __shfl_down_sync(0xffffffffu, acc[o], off);
        const int w = tid >> 5;
        if ((tid & 31) == 0) {
            #pragma unroll
            for (int o = 0; o < 10; o++) sm[OFF_A + w * 10 + o] = acc[o];
        }
        __syncthreads();
        if (tid < 10) {
            float s = 0.0f;
            #pragma unroll
            for (int ww = 0; ww < 7; ww++) s += sm[OFF_A + ww * 10 + tid];
            sm[OFF_OUT + tid] = s;
        }
        __syncthreads();
    }

    if (tid < 10) {
        float nrm = 0.0f;
        #pragma unroll
        for (int o = 0; o < 10; o++) { float t = sm[OFF_OUT + o]; nrm += t * t; }
        out[b * 10 + tid] = sm[OFF_OUT + tid] * rsqrtf(nrm);
    }
}

// ---------------------------------------------------------------------------
// launch
// ---------------------------------------------------------------------------

extern "C" void kernel_launch(void* const* d_in, const int* in_sizes, int n_in,
                              void* d_out, int out_size)
{
    const float* inputs = (const float*)d_in[0];   // (B,4,4,2)
    const float* peps   = (const float*)d_in[1];   // (4,4,2,6,6,6,6)
    const float* pepsc  = (const float*)d_in[2];   // (2,10,6,6,6,6)
    float* out = (float*)d_out;                    // (B,10)

    const int B = in_sizes[0] / 32;

    cudaFuncSetAttribute(peps_forward_kernel,
                         cudaFuncAttributeMaxDynamicSharedMemorySize, SMEM_BYTES);
    peps_forward_kernel<<<B, NT, SMEM_BYTES>>>(inputs, peps, pepsc, out, B);
}

// round 11
// speedup vs baseline: 1.6989x; 1.0484x over previous
#include <cuda_runtime.h>

#define NT 224

// shared-memory layout (float offsets)
#define OFF_A    0        // 7776  MPO ping / row ping-pong / R / warp partials
#define OFF_B    7776     // 7776  MPO pong / env0 / env_top / L2
#define OFF_N    15552    // 2592  node double-buffer: H0, H1 (also tgemm partials)
#define OFF_RED  18144    // 8
#define OFF_OUT  18152    // 12
#define OFF_X    18164    // 32
#define SMEM_FLOATS 18208
#define SMEM_BYTES  (SMEM_FLOATS * 4)

#define H0 (OFF_N)
#define H1 (OFF_N + 1296)

extern __shared__ float sm[];

// ---------------------------------------------------------------------------
// sumsq all-reduce
// ---------------------------------------------------------------------------

__device__ __forceinline__ void sumsq_publish(float v, int tid)
{
    #pragma unroll
    for (int o = 16; o > 0; o >>= 1) v += __shfl_down_sync(0xffffffffu, v, o);
    if ((tid & 31) == 0) sm[OFF_RED + (tid >> 5)] = v;
}

__device__ __forceinline__ float read_scale()
{
    float s = 0.0f;
    #pragma unroll
    for (int w = 0; w < 7; w++) s += sm[OFF_RED + w];
    return rsqrtf(s);
}

// ---------------------------------------------------------------------------
// node prefetch: COALESCED global reads (source-linear), permuted smem stores
// node = x0 * P[addr] + x1 * P[addr + 1296];  source tensor layout [u][r][d][l]
// ---------------------------------------------------------------------------

__device__ __forceinline__ void pf_full(float* v, const float* __restrict__ P,
                                        float x0, float x1, int tid)
{
    #pragma unroll
    for (int i = 0; i < 6; i++) {
        int k = tid + i * NT;
        if (k < 1296) v[i] = x0 * __ldg(P + k) + x1 * __ldg(P + k + 1296);
    }
}

__device__ __forceinline__ void st_full(int off, const float* v, int tid)
{
    #pragma unroll
    for (int i = 0; i < 6; i++) {
        int k = tid + i * NT;
        if (k < 1296) {
            int u = k / 216, rem = k % 216;
            int r = rem / 36;
            int d = (rem / 6) % 6;
            int l = rem % 6;
            sm[off + u * 216 + l * 36 + d * 6 + r] = v[i];
        }
    }
}

__device__ __forceinline__ float pf_l0(const float* __restrict__ P,
                                       float x0, float x1, int tid)
{
    if (tid >= 216) return 0.0f;
    int u = tid / 36, r = (tid / 6) % 6, d = tid % 6;
    int addr = u * 216 + r * 36 + d * 6;
    return x0 * __ldg(P + addr) + x1 * __ldg(P + addr + 1296);
}

__device__ __forceinline__ void st_l0(int off, float v, int tid, float scale)
{
    if (tid < 216) {
        int u = tid / 36, r = (tid / 6) % 6, d = tid % 6;
        sm[off + u * 36 + d * 6 + r] = v * scale;
    }
}

__device__ __forceinline__ float pf_r0(const float* __restrict__ P,
                                       float x0, float x1, int tid)
{
    if (tid >= 216) return 0.0f;
    int u = tid / 36, rest = tid % 36;        // rest = d*6 + l
    int addr = u * 216 + rest;
    return x0 * __ldg(P + addr) + x1 * __ldg(P + addr + 1296);
}

__device__ __forceinline__ void st_n13(int off, float v, int tid)
{
    if (tid < 216) {
        int u = tid / 36, rest = tid % 36;
        int d = rest / 6, l = rest % 6;
        sm[off + u * 36 + l * 6 + d] = v;
    }
}

__device__ __forceinline__ void st_n23(int off, float v, int tid, float scale)
{
    if (tid < 216) sm[off + tid] = v * scale;   // tid = u*36 + d*6 + l
}

__device__ __forceinline__ float pf_u0(const float* __restrict__ P,
                                       float x0, float x1, int tid)
{
    if (tid >= 216) return 0.0f;
    return x0 * __ldg(P + tid) + x1 * __ldg(P + tid + 1296);
}

__device__ __forceinline__ void st_id(int off, float v, int n, int tid)
{
    if (tid < n) sm[off + tid] = v;
}

__device__ __forceinline__ float pf_slice36(const float* __restrict__ P,
                                            float x0, float x1,
                                            int sa, int sb, int tid)
{
    if (tid >= 36) return 0.0f;
    int a = tid / 6, bb = tid % 6;
    int addr = a * sa + bb * sb;
    return x0 * __ldg(P + addr) + x1 * __ldg(P + addr + 1296);
}

__device__ __forceinline__ float pf_d0(const float* __restrict__ P,
                                       float x0, float x1, int tid)
{
    if (tid >= 216) return 0.0f;
    int u = tid / 36, r = (tid / 6) % 6, l = tid % 6;
    int addr = u * 216 + r * 36 + l;
    return x0 * __ldg(P + addr) + x1 * __ldg(P + addr + 1296);
}

// ---------------------------------------------------------------------------
// small-row helpers (rows 0 and 3)
// ---------------------------------------------------------------------------

__device__ __forceinline__ void rowstep(int outOff, int inOff, int nodeOff,
                                        int As, bool swap, int tid)
{
    const int n = As * 36;
    for (int k = tid; k < n; k += NT) {
        int A = k / 36;
        int p = (k / 6) % 6;
        int q = k % 6;
        int nb = (swap ? (p * 6 + q) : (q * 6 + p)) * 6;
        const float2* ip = (const float2*)(sm + inOff + A * 6);
        float2 i01 = ip[0], i23 = ip[1], i45 = ip[2];
        float acc = i01.x * sm[nodeOff + nb + 0] + i01.y * sm[nodeOff + nb + 1]
                  + i23.x * sm[nodeOff + nb + 2] + i23.y * sm[nodeOff + nb + 3]
                  + i45.x * sm[nodeOff + nb + 4] + i45.y * sm[nodeOff + nb + 5];
        sm[outOff + k] = acc;
    }
}

// 2-row laststep: thread handles A = 2tid, 2tid+1 (tid < 108)
__device__ __forceinline__ float laststep_sq_r2(int outOff, int inOff, int nodeOff, int tid)
{
    if (tid >= 108) return 0.0f;
    int A0 = tid * 2;
    const float2* ia = (const float2*)(sm + inOff + A0 * 6);
    float2 a01 = ia[0], a23 = ia[1], a45 = ia[2];
    const float2* ib = (const float2*)(sm + inOff + A0 * 6 + 6);
    float2 b01 = ib[0], b23 = ib[1], b45 = ib[2];
    float ss = 0.0f;
    #pragma unroll
    for (int p = 0; p < 6; p++) {
        const float2* np = (const float2*)(sm + nodeOff + p * 6);
        float2 n01 = np[0], n23 = np[1], n45 = np[2];
        float sA = a01.x * n01.x + a01.y * n01.y + a23.x * n23.x
                 + a23.y * n23.y + a45.x * n45.x + a45.y * n45.y;
        float sB = b01.x * n01.x + b01.y * n01.y + b23.x * n23.x
                 + b23.y * n23.y + b45.x * n45.x + b45.y * n45.y;
        ss += sA * sA + sB * sB;
        sm[outOff + A0 * 6 + p]     = sA;
        sm[outOff + (A0 + 1) * 6 + p] = sB;
    }
    return ss;
}

// 2-row transposed laststep: out[p*216 + (A/6)*6 + (A%6)]
__device__ __forceinline__ float laststep_T_sq_r2(int outOff, int inOff, int nodeOff, int tid)
{
    if (tid >= 108) return 0.0f;
    int A0 = tid * 2;
    const float2* ia = (const float2*)(sm + inOff + A0 * 6);
    float2 a01 = ia[0], a23 = ia[1], a45 = ia[2];
    const float2* ib = (const float2*)(sm + inOff + A0 * 6 + 6);
    float2 b01 = ib[0], b23 = ib[1], b45 = ib[2];
    int tA0 = (A0 / 6) * 6 + (A0 % 6);
    int tA1 = ((A0 + 1) / 6) * 6 + ((A0 + 1) % 6);
    float ss = 0.0f;
    #pragma unroll
    for (int p = 0; p < 6; p++) {
        const float2* np = (const float2*)(sm + nodeOff + p * 6);
        float2 n01 = np[0], n23 = np[1], n45 = np[2];
        float sA = a01.x * n01.x + a01.y * n01.y + a23.x * n23.x
                 + a23.y * n23.y + a45.x * n45.x + a45.y * n45.y;
        float sB = b01.x * n01.x + b01.y * n01.y + b23.x * n23.x
                 + b23.y * n23.y + b45.x * n45.x + b45.y * n45.y;
        ss += sA * sA + sB * sB;
        sm[outOff + p * 216 + tA0] = sA;
        sm[outOff + p * 216 + tA1] = sB;
    }
    return ss;
}

// ---------------------------------------------------------------------------
// MPO kernels
// ---------------------------------------------------------------------------

// mpo_first: 3(row) x 12(col) tiles, 216 threads (unchanged; cheap)
__device__ __forceinline__ void mpo_first36(int outOff, int eOff, int nodeOff, int tid)
{
    if (tid >= 216) return;
    const int rg = tid / 3;
    const int cg = tid % 3;
    float acc[3][12];
    #pragma unroll
    for (int rr = 0; rr < 3; rr++)
        #pragma unroll
        for (int j = 0; j < 12; j++) acc[rr][j] = 0.0f;
    #pragma unroll 1
    for (int u = 0; u < 6; u++) {
        float e[3];
        #pragma unroll
        for (int rr = 0; rr < 3; rr++) e[rr] = sm[eOff + u * 216 + rg * 3 + rr];
        const float4* nb = (const float4*)(sm + nodeOff + u * 36 + cg * 12);
        float4 n0 = nb[0], n1 = nb[1], n2 = nb[2];
        #pragma unroll
        for (int rr = 0; rr < 3; rr++) {
            acc[rr][0] += e[rr] * n0.x; acc[rr][1]  += e[rr] * n0.y;
            acc[rr][2] += e[rr] * n0.z; acc[rr][3]  += e[rr] * n0.w;
            acc[rr][4] += e[rr] * n1.x; acc[rr][5]  += e[rr] * n1.y;
            acc[rr][6] += e[rr] * n1.z; acc[rr][7]  += e[rr] * n1.w;
            acc[rr][8] += e[rr] * n2.x; acc[rr][9]  += e[rr] * n2.y;
            acc[rr][10]+= e[rr] * n2.z; acc[rr][11] += e[rr] * n2.w;
        }
    }
    #pragma unroll
    for (int rr = 0; rr < 3; rr++) {
        float4* out = (float4*)(sm + outOff + (rg * 3 + rr) * 36 + cg * 12);
        out[0] = make_float4(acc[rr][0], acc[rr][1], acc[rr][2], acc[rr][3]);
        out[1] = make_float4(acc[rr][4], acc[rr][5], acc[rr][6], acc[rr][7]);
        out[2] = make_float4(acc[rr][8], acc[rr][9], acc[rr][10], acc[rr][11]);
    }
}

// mpo_full: 4(row) x 12(col) tiles, 162 threads
// out[c*36 + b] = sum_{u,x} in[u*1296 + c*6 + x] * nodeL[(u*6+x)*36 + b]
__device__ __forceinline__ void mpo_full36_r4(int outOff, int inOff, int nodeOff, int tid)
{
    if (tid >= 162) return;
    const int rg = tid / 3;      // 0..53
    const int cg = tid % 3;
    float acc[4][12];
    #pragma unroll
    for (int rr = 0; rr < 4; rr++)
        #pragma unroll
        for (int j = 0; j < 12; j++) acc[rr][j] = 0.0f;
    #pragma unroll 1
    for (int u = 0; u < 6; u++) {
        float a[4][6];
        #pragma unroll
        for (int rr = 0; rr < 4; rr++) {
            const float2* sp = (const float2*)(sm + inOff + u * 1296 + (rg * 4 + rr) * 6);
            float2 s01 = sp[0], s23 = sp[1], s45 = sp[2];
            a[rr][0] = s01.x; a[rr][1] = s01.y;
            a[rr][2] = s23.x; a[rr][3] = s23.y;
            a[rr][4] = s45.x; a[rr][5] = s45.y;
        }
        #pragma unroll
        for (int x = 0; x < 6; x++) {
            const float4* nb = (const float4*)(sm + nodeOff + (u * 6 + x) * 36 + cg * 12);
            float4 n0 = nb[0], n1 = nb[1], n2 = nb[2];
            #pragma unroll
            for (int rr = 0; rr < 4; rr++) {
                float sv = a[rr][x];
                acc[rr][0] += sv * n0.x; acc[rr][1]  += sv * n0.y;
                acc[rr][2] += sv * n0.z; acc[rr][3]  += sv * n0.w;
                acc[rr][4] += sv * n1.x; acc[rr][5]  += sv * n1.y;
                acc[rr][6] += sv * n1.z; acc[rr][7]  += sv * n1.w;
                acc[rr][8] += sv * n2.x; acc[rr][9]  += sv * n2.y;
                acc[rr][10]+= sv * n2.z; acc[rr][11] += sv * n2.w;
            }
        }
    }
    #pragma unroll
    for (int rr = 0; rr < 4; rr++) {
        float4* out = (float4*)(sm + outOff + (rg * 4 + rr) * 36 + cg * 12);
        out[0] = make_float4(acc[rr][0], acc[rr][1], acc[rr][2], acc[rr][3]);
        out[1] = make_float4(acc[rr][4], acc[rr][5], acc[rr][6], acc[rr][7]);
        out[2] = make_float4(acc[rr][8], acc[rr][9], acc[rr][10], acc[rr][11]);
    }
}

// mpo_last: 2 c-rows per thread, 108 threads
// out[c*6 + d] = sum_{u,x} in[u*1296 + c*6 + x] * nodeLa[(u*6+x)*6 + d]
__device__ __forceinline__ float mpo_last36_sq_r2(int outOff, int inOff, int nodeOff, int tid)
{
    if (tid >= 108) return 0.0f;
    int c0 = tid * 2;
    float acc[2][6];
    #pragma unroll
    for (int r = 0; r < 2; r++)
        #pragma unroll
        for (int d = 0; d < 6; d++) acc[r][d] = 0.0f;
    #pragma unroll 1
    for (int u = 0; u < 6; u++) {
        const float2* sa = (const float2*)(sm + inOff + u * 1296 + c0 * 6);
        float2 A01 = sa[0], A23 = sa[1], A45 = sa[2];
        const float2* sb = (const float2*)(sm + inOff + u * 1296 + c0 * 6 + 6);
        float2 B01 = sb[0], B23 = sb[1], B45 = sb[2];
        float ax[6] = {A01.x, A01.y, A23.x, A23.y, A45.x, A45.y};
        float bx[6] = {B01.x, B01.y, B23.x, B23.y, B45.x, B45.y};
        #pragma unroll
        for (int x = 0; x < 6; x++) {
            const float2* nb = (const float2*)(sm + nodeOff + (u * 6 + x) * 6);
            float2 n01 = nb[0], n23 = nb[1], n45 = nb[2];
            float va = ax[x], vb = bx[x];
            acc[0][0] += va * n01.x; acc[0][1] += va * n01.y;
            acc[0][2] += va * n23.x; acc[0][3] += va * n23.y;
            acc[0][4] += va * n45.x; acc[0][5] += va * n45.y;
            acc[1][0] += vb * n01.x; acc[1][1] += vb * n01.y;
            acc[1][2] += vb * n23.x; acc[1][3] += vb * n23.y;
            acc[1][4] += vb * n45.x; acc[1][5] += vb * n45.y;
        }
    }
    float ss = 0.0f;
    #pragma unroll
    for (int r = 0; r < 2; r++) {
        float2* out = (float2*)(sm + outOff + (c0 + r) * 6);
        out[0] = make_float2(acc[r][0], acc[r][1]);
        out[1] = make_float2(acc[r][2], acc[r][3]);
        out[2] = make_float2(acc[r][4], acc[r][5]);
        #pragma unroll
        for (int d = 0; d < 6; d++) ss += acc[r][d] * acc[r][d];
    }
    return ss;
}

__device__ __noinline__ void rstep36(int outOff, int ebOff, int nodeOff, int tid)
{
    if (tid >= 216) return;
    int u3 = tid / 36;
    int dd = tid % 36;
    float acc[36];
    #pragma unroll
    for (int i = 0; i < 36; i++) acc[i] = 0.0f;
    #pragma unroll 1
    for (int d3 = 0; d3 < 6; d3++) {
        const float2* ep = (const float2*)(sm + ebOff + d3 * 216 + dd * 6);
        float2 e01 = ep[0], e23 = ep[1], e45 = ep[2];
        float eb[6] = {e01.x, e01.y, e23.x, e23.y, e45.x, e45.y};
        const float2* np = (const float2*)(sm + nodeOff + u3 * 36 + d3 * 6);
        float2 n01 = np[0], n23v = np[1], n45 = np[2];
        float nv[6] = {n01.x, n01.y, n23v.x, n23v.y, n45.x, n45.y};
        #pragma unroll
        for (int d2 = 0; d2 < 6; d2++)
            #pragma unroll
            for (int l3 = 0; l3 < 6; l3++)
                acc[d2 * 6 + l3] += eb[d2] * nv[l3];
    }
    float4* out = (float4*)(sm + outOff + tid * 36);
    #pragma unroll
    for (int q = 0; q < 9; q++)
        out[q] = make_float4(acc[q*4], acc[q*4+1], acc[q*4+2], acc[q*4+3]);
}

// tgemm: T[u*216 + r*36 + d*6 + l] = sum_m L[u*1296 + m*6 + l] * R[m*36 + d*6 + r]
// 2-way m-split (groups of 72 threads), 3(l) x 6(r) tile, d = bg fixed per thread.
// Partials: group 0 -> t0Off (H0), group 1 -> t1Off (H1); summed by consumer.
__device__ __noinline__ void tgemm_split(int t0Off, int t1Off, int lOff, int rOff, int tid)
{
    if (tid >= 144) return;
    int grp = tid / 72;
    int t   = tid % 72;
    int u   = t / 12;           // 0..5
    int lg  = (t / 6) % 2;      // 0..1
    int bg  = t % 6;            // 0..5 (= d)
    int l0  = lg * 3;
    int b0  = bg * 6;
    float acc[3][6];
    #pragma unroll
    for (int i = 0; i < 3; i++)
        #pragma unroll
        for (int j = 0; j < 6; j++) acc[i][j] = 0.0f;
    const float* Lp = sm + lOff + u * 1296 + l0;
    const float* Rp = sm + rOff + b0;
    const int m0 = grp * 108;
    #pragma unroll 4
    for (int mm = 0; mm < 108; mm++) {
        int m = m0 + mm;
        float a0 = Lp[m * 6 + 0];
        float a1 = Lp[m * 6 + 1];
        float a2 = Lp[m * 6 + 2];
        float2 b01 = *(const float2*)(Rp + m * 36);
        float2 b23 = *(const float2*)(Rp + m * 36 + 2);
        float2 b45 = *(const float2*)(Rp + m * 36 + 4);
        acc[0][0] += a0 * b01.x; acc[0][1] += a0 * b01.y;
        acc[0][2] += a0 * b23.x; acc[0][3] += a0 * b23.y;
        acc[0][4] += a0 * b45.x; acc[0][5] += a0 * b45.y;
        acc[1][0] += a1 * b01.x; acc[1][1] += a1 * b01.y;
        acc[1][2] += a1 * b23.x; acc[1][3] += a1 * b23.y;
        acc[1][4] += a1 * b45.x; acc[1][5] += a1 * b45.y;
        acc[2][0] += a2 * b01.x; acc[2][1] += a2 * b01.y;
        acc[2][2] += a2 * b23.x; acc[2][3] += a2 * b23.y;
        acc[2][4] += a2 * b45.x; acc[2][5] += a2 * b45.y;
    }
    int dst = (grp == 0) ? t0Off : t1Off;
    #pragma unroll
    for (int r = 0; r < 6; r++)
        #pragma unroll
        for (int li = 0; li < 3; li++)
            sm[dst + u * 216 + r * 36 + bg * 6 + l0 + li] = acc[li][r];
}

// ---------------------------------------------------------------------------
// kernel
// ---------------------------------------------------------------------------

__global__ __launch_bounds__(NT, 3)
void peps_forward_kernel(const float* __restrict__ inputs,
                         const float* __restrict__ peps,
                         const float* __restrict__ pepsc,
                         float* __restrict__ out, int B)
{
    const int tid = threadIdx.x;
    const int b = blockIdx.x;

    if (tid < 32) sm[OFF_X + tid] = inputs[b * 32 + tid];
    __syncthreads();

    #define PB(i, j)  (peps + ((i) * 4 + (j)) * 2 * 1296)
    #define XX0(i, j) sm[OFF_X + ((i) * 4 + (j)) * 2]
    #define XX1(i, j) sm[OFF_X + ((i) * 4 + (j)) * 2 + 1]

    const int P0 = OFF_A;
    const int P1 = OFF_A + 1296;
    float vf[6];

    // ---- init: n00 (u=0,l=0, transposed into P0) + n01 -> H1 ----
    {
        float v00 = pf_slice36(PB(0, 0), XX0(0, 0), XX1(0, 0), 36, 6, tid); // (r,d)
        float v01 = pf_u0(PB(0, 1), XX0(0, 1), XX1(0, 1), tid);
        if (tid < 36) sm[P0 + (tid % 6) * 6 + (tid / 6)] = v00;  // P0[d*6+r]
        st_id(H1, v01, 216, tid);
    }
    __syncthreads();
    // step: rowstep with n01; prefetch n02
    {
        float v = pf_u0(PB(0, 2), XX0(0, 2), XX1(0, 2), tid);
        rowstep(P1, P0, H1, 6, false, tid);
        st_id(H0, v, 216, tid);
    }
    __syncthreads();
    // step: rowstep with n02; prefetch n03 (u=0,r=0 -> (d,l) identity)
    {
        float v = pf_slice36(PB(0, 3), XX0(0, 3), XX1(0, 3), 6, 1, tid);
        rowstep(P0, P1, H0, 36, false, tid);
        st_id(H1, v, 36, tid);
    }
    __syncthreads();
    // step: env0 raw -> B ; scale into n10 [u][d][r]
    {
        float v = pf_l0(PB(1, 0), XX0(1, 0), XX1(1, 0), tid);
        float ss = laststep_sq_r2(OFF_B, P0, H1, tid);
        sumsq_publish(ss, tid);
        __syncthreads();
        float sc = read_scale();
        st_l0(H0, v, tid, sc);
    }
    __syncthreads();

    // ================= Row 1 =================
    {
        pf_full(vf, PB(1, 1), XX0(1, 1), XX1(1, 1), tid);
        mpo_first36(OFF_A, OFF_B, H0, tid);
        st_full(H1, vf, tid);
    }
    __syncthreads();
    {
        pf_full(vf, PB(1, 2), XX0(1, 2), XX1(1, 2), tid);
        mpo_full36_r4(OFF_B, OFF_A, H1, tid);
        st_full(H0, vf, tid);
    }
    __syncthreads();
    {
        float v = pf_r0(PB(1, 3), XX0(1, 3), XX1(1, 3), tid);
        mpo_full36_r4(OFF_A, OFF_B, H0, tid);
        st_n13(H1, v, tid);
    }
    __syncthreads();
    {
        float v = pf_l0(PB(2, 0), XX0(2, 0), XX1(2, 0), tid);
        float ss = mpo_last36_sq_r2(OFF_B, OFF_A, H1, tid);
        sumsq_publish(ss, tid);
        __syncthreads();
        float sc = read_scale();
        st_l0(H0, v, tid, sc);
    }
    __syncthreads();

    // ================= Row 2 L-part =================
    {
        pf_full(vf, PB(2, 1), XX0(2, 1), XX1(2, 1), tid);
        mpo_first36(OFF_A, OFF_B, H0, tid);
        st_full(H1, vf, tid);
    }
    __syncthreads();
    {
        float v = pf_slice36(PB(3, 0), XX0(3, 0), XX1(3, 0), 216, 36, tid); // (u,r)
        mpo_full36_r4(OFF_B, OFF_A, H1, tid);   // L2 -> B (persists)
        st_id(H0, v, 36, tid);
    }
    __syncthreads();

    // ================= Row 3 (ping-pong in A; B holds L2) =================
    {
        float v = pf_d0(PB(3, 1), XX0(3, 1), XX1(3, 1), tid);   // [u][r][l]
        if (tid < 36) sm[P0 + tid] = sm[H0 + tid];
        st_id(H1, v, 216, tid);
    }
    __syncthreads();
    {
        float v = pf_d0(PB(3, 2), XX0(3, 2), XX1(3, 2), tid);
        rowstep(P1, P0, H1, 6, true, tid);
        st_id(H0, v, 216, tid);
    }
    __syncthreads();
    {
        float v = pf_slice36(PB(3, 3), XX0(3, 3), XX1(3, 3), 216, 1, tid);  // (u,l)
        rowstep(P0, P1, H0, 36, true, tid);
        st_id(H0 + 432, v, 36, tid);
    }
    __syncthreads();
    {
        float v = pf_r0(PB(2, 3), XX0(2, 3), XX1(2, 3), tid);   // identity [u][d][l]
        float ss = laststep_T_sq_r2(H1, P0, H0 + 432, tid);
        sumsq_publish(ss, tid);
        __syncthreads();
        float sc = read_scale();
        st_n23(H0, v, tid, sc);
    }
    __syncthreads();

    // ================= R-part + merge =================
    rstep36(OFF_A, H1, H0, tid);              // R -> A (consumes H0=n23, H1=env_botT)
    __syncthreads();
    tgemm_split(H0, H1, OFF_B, OFF_A, tid);   // partials -> H0, H1
    __syncthreads();

    // ================= Final contraction with peps_center (float4) ========
    {
        const float xc0 = XX0(2, 2);
        const float xc1 = XX1(2, 2);
        float acc[10];
        #pragma unroll
        for (int o = 0; o < 10; o++) acc[o] = 0.0f;
        for (int kk = tid * 4; kk < 1296; kk += NT * 4) {
            const float4 t0 = *(const float4*)(sm + H0 + kk);
            const float4 t1 = *(const float4*)(sm + H1 + kk);
            float4 e4 = make_float4(t0.x + t1.x, t0.y + t1.y, t0.z + t1.z, t0.w + t1.w);
            float4 e0 = make_float4(e4.x * xc0, e4.y * xc0, e4.z * xc0, e4.w * xc0);
            float4 e1 = make_float4(e4.x * xc1, e4.y * xc1, e4.z * xc1, e4.w * xc1);
            #pragma unroll
            for (int o = 0; o < 10; o++) {
                float4 p0 = __ldg((const float4*)(pepsc + o * 1296 + kk));
                float4 p1 = __ldg((const float4*)(pepsc + 12960 + o * 1296 + kk));
                acc[o] += e0.x * p0.x + e0.y * p0.y + e0.z * p0.z + e0.w * p0.w
                        + e1.x * p1.x + e1.y * p1.y + e1.z * p1.z + e1.w * p1.w;
            }
        }
        #pragma unroll
        for (int o = 0; o < 10; o++)
            #pragma unroll
            for (int off = 16; off > 0; off >>= 1)
                acc[o] += __shfl_down_sync(0xffffffffu, acc[o], off);
        const int w = tid >> 5;
        if ((tid & 31) == 0) {
            #pragma unroll
            for (int o = 0; o < 10; o++) sm[OFF_A + w * 10 + o] = acc[o];
        }
        __syncthreads();
        if (tid < 10) {
            float s = 0.0f;
            #pragma unroll
            for (int ww = 0; ww < 7; ww++) s += sm[OFF_A + ww * 10 + tid];
            sm[OFF_OUT + tid] = s;
        }
        __syncthreads();
    }

    if (tid < 10) {
        float nrm = 0.0f;
        #pragma unroll
        for (int o = 0; o < 10; o++) { float t = sm[OFF_OUT + o]; nrm += t * t; }
        out[b * 10 + tid] = sm[OFF_OUT + tid] * rsqrtf(nrm);
    }
}

// ---------------------------------------------------------------------------
// launch
// ---------------------------------------------------------------------------

extern "C" void kernel_launch(void* const* d_in, const int* in_sizes, int n_in,
                              void* d_out, int out_size)
{
    const float* inputs = (const float*)d_in[0];   // (B,4,4,2)
    const float* peps   = (const float*)d_in[1];   // (4,4,2,6,6,6,6)
    const float* pepsc  = (const float*)d_in[2];   // (2,10,6,6,6,6)
    float* out = (float*)d_out;                    // (B,10)

    const int B = in_sizes[0] / 32;

    cudaFuncSetAttribute(peps_forward_kernel,
                         cudaFuncAttributeMaxDynamicSharedMemorySize, SMEM_BYTES);
    peps_forward_kernel<<<B, NT, SMEM_BYTES>>>(inputs, peps, pepsc, out, B);
}

// round 14
// speedup vs baseline: 1.8020x; 1.0607x over previous
#include <cuda_runtime.h>

#define NT 224

// shared-memory layout (float offsets) — single 7776 state buffer, in-place MPO
#define S_OFF    0        // 7776  MPO state / L2 / M (in-place)
#define E_OFF    7776     // 1296  env0 / env_top / env_botT / T
#define P0       9072     // 1296  row0/row3 ping
#define P1       10368    // 1296  row0/row3 pong
#define H0       11664    // 1296  node buffer A
#define H1       12960    // 1296  node buffer B
#define OFF_RED  14256    // 8
#define OFF_OUT  14264    // 12
#define OFF_X    14276    // 32
#define SMEM_FLOATS 14308
#define SMEM_BYTES  (SMEM_FLOATS * 4)

extern __shared__ float sm[];

// ---------------------------------------------------------------------------
// sumsq all-reduce
// ---------------------------------------------------------------------------

__device__ __forceinline__ void sumsq_publish(float v, int tid)
{
    #pragma unroll
    for (int o = 16; o > 0; o >>= 1) v += __shfl_down_sync(0xffffffffu, v, o);
    if ((tid & 31) == 0) sm[OFF_RED + (tid >> 5)] = v;
}

__device__ __forceinline__ float read_scale()
{
    float s = 0.0f;
    #pragma unroll
    for (int w = 0; w < 7; w++) s += sm[OFF_RED + w];
    return rsqrtf(s);
}

// ---------------------------------------------------------------------------
// node prefetch (coalesced LDG) + permuted smem stores
// node = x0 * P[addr] + x1 * P[addr + 1296];  source layout [u][r][d][l]
// ---------------------------------------------------------------------------

__device__ __forceinline__ void pf_full(float* v, const float* __restrict__ P,
                                        float x0, float x1, int tid)
{
    #pragma unroll
    for (int i = 0; i < 6; i++) {
        int k = tid + i * NT;
        if (k < 1296) v[i] = x0 * __ldg(P + k) + x1 * __ldg(P + k + 1296);
    }
}

__device__ __forceinline__ void st_full(int off, const float* v, int tid)
{
    #pragma unroll
    for (int i = 0; i < 6; i++) {
        int k = tid + i * NT;
        if (k < 1296) {
            int u = k / 216, rem = k % 216;
            int r = rem / 36;
            int d = (rem / 6) % 6;
            int l = rem % 6;
            sm[off + u * 216 + l * 36 + d * 6 + r] = v[i];
        }
    }
}

__device__ __forceinline__ float pf_l0(const float* __restrict__ P,
                                       float x0, float x1, int tid)
{
    if (tid >= 216) return 0.0f;
    int u = tid / 36, r = (tid / 6) % 6, d = tid % 6;
    int addr = u * 216 + r * 36 + d * 6;
    return x0 * __ldg(P + addr) + x1 * __ldg(P + addr + 1296);
}

__device__ __forceinline__ void st_l0(int off, float v, int tid, float scale)
{
    if (tid < 216) {
        int u = tid / 36, r = (tid / 6) % 6, d = tid % 6;
        sm[off + u * 36 + d * 6 + r] = v * scale;
    }
}

__device__ __forceinline__ float pf_r0(const float* __restrict__ P,
                                       float x0, float x1, int tid)
{
    if (tid >= 216) return 0.0f;
    int u = tid / 36, rest = tid % 36;        // rest = d*6 + l
    int addr = u * 216 + rest;
    return x0 * __ldg(P + addr) + x1 * __ldg(P + addr + 1296);
}

__device__ __forceinline__ void st_n13(int off, float v, int tid)
{
    if (tid < 216) {
        int u = tid / 36, rest = tid % 36;
        int d = rest / 6, l = rest % 6;
        sm[off + u * 36 + l * 6 + d] = v;
    }
}

__device__ __forceinline__ void st_n23(int off, float v, int tid, float scale)
{
    if (tid < 216) sm[off + tid] = v * scale;   // tid = u*36 + d*6 + l
}

__device__ __forceinline__ float pf_u0(const float* __restrict__ P,
                                       float x0, float x1, int tid)
{
    if (tid >= 216) return 0.0f;
    return x0 * __ldg(P + tid) + x1 * __ldg(P + tid + 1296);
}

__device__ __forceinline__ void st_id(int off, float v, int n, int tid)
{
    if (tid < n) sm[off + tid] = v;
}

__device__ __forceinline__ float pf_slice36(const float* __restrict__ P,
                                            float x0, float x1,
                                            int sa, int sb, int tid)
{
    if (tid >= 36) return 0.0f;
    int a = tid / 6, bb = tid % 6;
    int addr = a * sa + bb * sb;
    return x0 * __ldg(P + addr) + x1 * __ldg(P + addr + 1296);
}

__device__ __forceinline__ float pf_d0(const float* __restrict__ P,
                                       float x0, float x1, int tid)
{
    if (tid >= 216) return 0.0f;
    int u = tid / 36, r = (tid / 6) % 6, l = tid % 6;
    int addr = u * 216 + r * 36 + l;
    return x0 * __ldg(P + addr) + x1 * __ldg(P + addr + 1296);
}

// ---------------------------------------------------------------------------
// small-row helpers (rows 0 and 3)
// ---------------------------------------------------------------------------

__device__ __forceinline__ void rowstep(int outOff, int inOff, int nodeOff,
                                        int As, bool swap, int tid)
{
    const int n = As * 36;
    for (int k = tid; k < n; k += NT) {
        int A = k / 36;
        int p = (k / 6) % 6;
        int q = k % 6;
        int nb = (swap ? (p * 6 + q) : (q * 6 + p)) * 6;
        const float2* ip = (const float2*)(sm + inOff + A * 6);
        float2 i01 = ip[0], i23 = ip[1], i45 = ip[2];
        float acc = i01.x * sm[nodeOff + nb + 0] + i01.y * sm[nodeOff + nb + 1]
                  + i23.x * sm[nodeOff + nb + 2] + i23.y * sm[nodeOff + nb + 3]
                  + i45.x * sm[nodeOff + nb + 4] + i45.y * sm[nodeOff + nb + 5];
        sm[outOff + k] = acc;
    }
}

__device__ __forceinline__ float laststep_sq_r2(int outOff, int inOff, int nodeOff, int tid)
{
    if (tid >= 108) return 0.0f;
    int A0 = tid * 2;
    const float2* ia = (const float2*)(sm + inOff + A0 * 6);
    float2 a01 = ia[0], a23 = ia[1], a45 = ia[2];
    const float2* ib = (const float2*)(sm + inOff + A0 * 6 + 6);
    float2 b01 = ib[0], b23 = ib[1], b45 = ib[2];
    float ss = 0.0f;
    #pragma unroll
    for (int p = 0; p < 6; p++) {
        const float2* np = (const float2*)(sm + nodeOff + p * 6);
        float2 n01 = np[0], n23 = np[1], n45 = np[2];
        float sA = a01.x * n01.x + a01.y * n01.y + a23.x * n23.x
                 + a23.y * n23.y + a45.x * n45.x + a45.y * n45.y;
        float sB = b01.x * n01.x + b01.y * n01.y + b23.x * n23.x
                 + b23.y * n23.y + b45.x * n45.x + b45.y * n45.y;
        ss += sA * sA + sB * sB;
        sm[outOff + A0 * 6 + p]       = sA;
        sm[outOff + (A0 + 1) * 6 + p] = sB;
    }
    return ss;
}

// transposed: out[p*216 + A]
__device__ __forceinline__ float laststep_T_sq_r2(int outOff, int inOff, int nodeOff, int tid)
{
    if (tid >= 108) return 0.0f;
    int A0 = tid * 2;
    const float2* ia = (const float2*)(sm + inOff + A0 * 6);
    float2 a01 = ia[0], a23 = ia[1], a45 = ia[2];
    const float2* ib = (const float2*)(sm + inOff + A0 * 6 + 6);
    float2 b01 = ib[0], b23 = ib[1], b45 = ib[2];
    float ss = 0.0f;
    #pragma unroll
    for (int p = 0; p < 6; p++) {
        const float2* np = (const float2*)(sm + nodeOff + p * 6);
        float2 n01 = np[0], n23 = np[1], n45 = np[2];
        float sA = a01.x * n01.x + a01.y * n01.y + a23.x * n23.x
                 + a23.y * n23.y + a45.x * n45.x + a45.y * n45.y;
        float sB = b01.x * n01.x + b01.y * n01.y + b23.x * n23.x
                 + b23.y * n23.y + b45.x * n45.x + b45.y * n45.y;
        ss += sA * sA + sB * sB;
        sm[outOff + p * 216 + A0]     = sA;
        sm[outOff + p * 216 + A0 + 1] = sB;
    }
    return ss;
}

// ---------------------------------------------------------------------------
// MPO kernels
// ---------------------------------------------------------------------------

// mpo_first: out[c*36+b] = sum_u E[u*216+c] * node[u*36+b] ; 3x12 tiles, 216 thr
__device__ __forceinline__ void mpo_first36(int outOff, int eOff, int nodeOff, int tid)
{
    if (tid >= 216) return;
    const int rg = tid / 3;
    const int cg = tid % 3;
    float acc[3][12];
    #pragma unroll
    for (int rr = 0; rr < 3; rr++)
        #pragma unroll
        for (int j = 0; j < 12; j++) acc[rr][j] = 0.0f;
    #pragma unroll 1
    for (int u = 0; u < 6; u++) {
        float e[3];
        #pragma unroll
        for (int rr = 0; rr < 3; rr++) e[rr] = sm[eOff + u * 216 + rg * 3 + rr];
        const float4* nb = (const float4*)(sm + nodeOff + u * 36 + cg * 12);
        float4 n0 = nb[0], n1 = nb[1], n2 = nb[2];
        #pragma unroll
        for (int rr = 0; rr < 3; rr++) {
            acc[rr][0] += e[rr] * n0.x; acc[rr][1]  += e[rr] * n0.y;
            acc[rr][2] += e[rr] * n0.z; acc[rr][3]  += e[rr] * n0.w;
            acc[rr][4] += e[rr] * n1.x; acc[rr][5]  += e[rr] * n1.y;
            acc[rr][6] += e[rr] * n1.z; acc[rr][7]  += e[rr] * n1.w;
            acc[rr][8] += e[rr] * n2.x; acc[rr][9]  += e[rr] * n2.y;
            acc[rr][10]+= e[rr] * n2.z; acc[rr][11] += e[rr] * n2.w;
        }
    }
    #pragma unroll
    for (int rr = 0; rr < 3; rr++) {
        float4* out = (float4*)(sm + outOff + (rg * 3 + rr) * 36 + cg * 12);
        out[0] = make_float4(acc[rr][0], acc[rr][1], acc[rr][2], acc[rr][3]);
        out[1] = make_float4(acc[rr][4], acc[rr][5], acc[rr][6], acc[rr][7]);
        out[2] = make_float4(acc[rr][8], acc[rr][9], acc[rr][10], acc[rr][11]);
    }
}

// mpo_full split into acc / st for IN-PLACE use (sync lives in kernel body).
// acc[c'][b] = sum_{u,x} S[u*1296 + c*6 + x] * node[(u*6+x)*36 + b]; 3x12, 216 thr
__device__ __forceinline__ void mpo_full_acc(float* acc, int inOff, int nodeOff, int tid)
{
    if (tid >= 216) return;
    const int rg = tid / 3;
    const int cg = tid % 3;
    #pragma unroll
    for (int i = 0; i < 36; i++) acc[i] = 0.0f;
    #pragma unroll 1
    for (int u = 0; u < 6; u++) {
        float a[3][6];
        #pragma unroll
        for (int rr = 0; rr < 3; rr++) {
            const float2* sp = (const float2*)(sm + inOff + u * 1296 + (rg * 3 + rr) * 6);
            float2 s01 = sp[0], s23 = sp[1], s45 = sp[2];
            a[rr][0] = s01.x; a[rr][1] = s01.y;
            a[rr][2] = s23.x; a[rr][3] = s23.y;
            a[rr][4] = s45.x; a[rr][5] = s45.y;
        }
        #pragma unroll
        for (int x = 0; x < 6; x++) {
            const float4* nb = (const float4*)(sm + nodeOff + (u * 6 + x) * 36 + cg * 12);
            float4 n0 = nb[0], n1 = nb[1], n2 = nb[2];
            #pragma unroll
            for (int rr = 0; rr < 3; rr++) {
                float sv = a[rr][x];
                float* ar = acc + rr * 12;
                ar[0] += sv * n0.x; ar[1]  += sv * n0.y;
                ar[2] += sv * n0.z; ar[3]  += sv * n0.w;
                ar[4] += sv * n1.x; ar[5]  += sv * n1.y;
                ar[6] += sv * n1.z; ar[7]  += sv * n1.w;
                ar[8] += sv * n2.x; ar[9]  += sv * n2.y;
                ar[10]+= sv * n2.z; ar[11] += sv * n2.w;
            }
        }
    }
}

__device__ __forceinline__ void mpo_full_st(const float* acc, int outOff, int tid)
{
    if (tid >= 216) return;
    const int rg = tid / 3;
    const int cg = tid % 3;
    #pragma unroll
    for (int rr = 0; rr < 3; rr++) {
        const float* ar = acc + rr * 12;
        float4* out = (float4*)(sm + outOff + (rg * 3 + rr) * 36 + cg * 12);
        out[0] = make_float4(ar[0], ar[1], ar[2],  ar[3]);
        out[1] = make_float4(ar[4], ar[5], ar[6],  ar[7]);
        out[2] = make_float4(ar[8], ar[9], ar[10], ar[11]);
    }
}

// mpo_last: 2 rows/thread, 108 thr
__device__ __forceinline__ float mpo_last36_sq_r2(int outOff, int inOff, int nodeOff, int tid)
{
    if (tid >= 108) return 0.0f;
    int c0 = tid * 2;
    float acc[2][6];
    #pragma unroll
    for (int r = 0; r < 2; r++)
        #pragma unroll
        for (int d = 0; d < 6; d++) acc[r][d] = 0.0f;
    #pragma unroll 1
    for (int u = 0; u < 6; u++) {
        const float2* sa = (const float2*)(sm + inOff + u * 1296 + c0 * 6);
        float2 A01 = sa[0], A23 = sa[1], A45 = sa[2];
        const float2* sb = (const float2*)(sm + inOff + u * 1296 + c0 * 6 + 6);
        float2 B01 = sb[0], B23 = sb[1], B45 = sb[2];
        float ax[6] = {A01.x, A01.y, A23.x, A23.y, A45.x, A45.y};
        float bx[6] = {B01.x, B01.y, B23.x, B23.y, B45.x, B45.y};
        #pragma unroll
        for (int x = 0; x < 6; x++) {
            const float2* nb = (const float2*)(sm + nodeOff + (u * 6 + x) * 6);
            float2 n01 = nb[0], n23 = nb[1], n45 = nb[2];
            float va = ax[x], vb = bx[x];
            acc[0][0] += va * n01.x; acc[0][1] += va * n01.y;
            acc[0][2] += va * n23.x; acc[0][3] += va * n23.y;
            acc[0][4] += va * n45.x; acc[0][5] += va * n45.y;
            acc[1][0] += vb * n01.x; acc[1][1] += vb * n01.y;
            acc[1][2] += vb * n23.x; acc[1][3] += vb * n23.y;
            acc[1][4] += vb * n45.x; acc[1][5] += vb * n45.y;
        }
    }
    float ss = 0.0f;
    #pragma unroll
    for (int r = 0; r < 2; r++) {
        float2* out = (float2*)(sm + outOff + (c0 + r) * 6);
        out[0] = make_float2(acc[r][0], acc[r][1]);
        out[1] = make_float2(acc[r][2], acc[r][3]);
        out[2] = make_float2(acc[r][4], acc[r][5]);
        #pragma unroll
        for (int d = 0; d < 6; d++) ss += acc[r][d] * acc[r][d];
    }
    return ss;
}

// ---------------------------------------------------------------------------
// fused R/tgemm replacement (in-place over S):
// step1: M[u2][u3][d3][d2][l2] = sum_d0d1 L[u2][u3][d0d1][l2] * EbT[d3][d0d1][d2]
// step2: T[u2][l3][d2][l2] = sum_{u3,d3} M[u2][u3][d3][d2][l2] * n23[u3][d3][l3]
// ---------------------------------------------------------------------------

__device__ __forceinline__ void step1_acc(float* acc, int sOff, int eOff, int tid)
{
    if (tid >= 216) return;
    const int u2 = tid / 36, u3 = (tid / 6) % 6, d3 = tid % 6;
    #pragma unroll
    for (int i = 0; i < 36; i++) acc[i] = 0.0f;
    const float* Lb = sm + sOff + u2 * 1296 + u3 * 216;   // + d0d1*6 + l2
    const float* Eb = sm + eOff + d3 * 216;               // + d0d1*6 + d2
    #pragma unroll 4
    for (int dd = 0; dd < 36; dd++) {
        const float2* lp = (const float2*)(Lb + dd * 6);
        float2 l01 = lp[0], l23 = lp[1], l45 = lp[2];
        float L6[6] = {l01.x, l01.y, l23.x, l23.y, l45.x, l45.y};
        const float2* ep = (const float2*)(Eb + dd * 6);
        float2 e01 = ep[0], e23 = ep[1], e45 = ep[2];
        float E6[6] = {e01.x, e01.y, e23.x, e23.y, e45.x, e45.y};
        #pragma unroll
        for (int d2 = 0; d2 < 6; d2++)
            #pragma unroll
            for (int l2 = 0; l2 < 6; l2++)
                acc[d2 * 6 + l2] += E6[d2] * L6[l2];
    }
}

__device__ __forceinline__ void step1_st(const float* acc, int sOff, int tid)
{
    if (tid >= 216) return;
    const int u2 = tid / 36, u3 = (tid / 6) % 6, d3 = tid % 6;
    float4* out = (float4*)(sm + sOff + u2 * 1296 + u3 * 216 + d3 * 36);
    #pragma unroll
    for (int q = 0; q < 9; q++)
        out[q] = make_float4(acc[q*4], acc[q*4+1], acc[q*4+2], acc[q*4+3]);
}

__device__ __forceinline__ void step2(int tOff, int sOff, int nOff, int tid)
{
    if (tid >= 216) return;
    const int u2 = tid / 36, d2 = (tid / 6) % 6, l2 = tid % 6;
    float acc[6] = {0, 0, 0, 0, 0, 0};
    const float* Mp = sm + sOff + u2 * 1296 + d2 * 6 + l2;
    #pragma unroll 4
    for (int ud = 0; ud < 36; ud++) {       // ud = u3*6 + d3
        float m = Mp[ud * 36];
        const float2* np = (const float2*)(sm + nOff + ud * 6);
        float2 n01 = np[0], n23 = np[1], n45 = np[2];
        acc[0] += m * n01.x; acc[1] += m * n01.y;
        acc[2] += m * n23.x; acc[3] += m * n23.y;
        acc[4] += m * n45.x; acc[5] += m * n45.y;
    }
    #pragma unroll
    for (int l3 = 0; l3 < 6; l3++)
        sm[tOff + u2 * 216 + l3 * 36 + d2 * 6 + l2] = acc[l3];
}

// ---------------------------------------------------------------------------
// kernel: one block per batch element, single in-place state buffer, 4 CTAs/SM
// ---------------------------------------------------------------------------

__global__ __launch_bounds__(NT, 4)
void peps_forward_kernel(const float* __restrict__ inputs,
                         const float* __restrict__ peps,
                         const float* __restrict__ pepsc,
                         float* __restrict__ out, int B)
{
    const int tid = threadIdx.x;
    const int b = blockIdx.x;

    if (tid < 32) sm[OFF_X + tid] = inputs[b * 32 + tid];
    __syncthreads();

    #define PB(i, j)  (peps + ((i) * 4 + (j)) * 2 * 1296)
    #define XX0(i, j) sm[OFF_X + ((i) * 4 + (j)) * 2]
    #define XX1(i, j) sm[OFF_X + ((i) * 4 + (j)) * 2 + 1]

    float vf[6];
    float acc36[36];

    // ================= Row 0 (state P0/P1, nodes H0/H1) =================
    {
        float v00 = pf_slice36(PB(0, 0), XX0(0, 0), XX1(0, 0), 36, 6, tid); // (r,d)
        float v01 = pf_u0(PB(0, 1), XX0(0, 1), XX1(0, 1), tid);
        if (tid < 36) sm[P0 + (tid % 6) * 6 + (tid / 6)] = v00;  // P0[d*6+r]
        st_id(H1, v01, 216, tid);
    }
    __syncthreads();
    {
        float v = pf_u0(PB(0, 2), XX0(0, 2), XX1(0, 2), tid);
        rowstep(P1, P0, H1, 6, false, tid);
        st_id(H0, v, 216, tid);
    }
    __syncthreads();
    {
        float v = pf_slice36(PB(0, 3), XX0(0, 3), XX1(0, 3), 6, 1, tid);
        rowstep(P0, P1, H0, 36, false, tid);
        st_id(H1, v, 36, tid);
    }
    __syncthreads();
    {
        float v = pf_l0(PB(1, 0), XX0(1, 0), XX1(1, 0), tid);
        float ss = laststep_sq_r2(E_OFF, P0, H1, tid);   // env0 raw -> E
        sumsq_publish(ss, tid);
        __syncthreads();
        float sc = read_scale();
        st_l0(H0, v, tid, sc);                           // n10 scaled
    }
    __syncthreads();

    // ================= Row 1 (state S, in-place) =================
    {
        pf_full(vf, PB(1, 1), XX0(1, 1), XX1(1, 1), tid);
        mpo_first36(S_OFF, E_OFF, H0, tid);              // S <- env0 x n10
        st_full(H1, vf, tid);
    }
    __syncthreads();
    {
        pf_full(vf, PB(1, 2), XX0(1, 2), XX1(1, 2), tid);
        mpo_full_acc(acc36, S_OFF, H1, tid);
        __syncthreads();
        mpo_full_st(acc36, S_OFF, tid);                  // in-place
        st_full(H0, vf, tid);
    }
    __syncthreads();
    {
        float v = pf_r0(PB(1, 3), XX0(1, 3), XX1(1, 3), tid);
        mpo_full_acc(acc36, S_OFF, H0, tid);
        __syncthreads();
        mpo_full_st(acc36, S_OFF, tid);                  // in-place
        st_n13(H1, v, tid);
    }
    __syncthreads();
    {
        float v = pf_l0(PB(2, 0), XX0(2, 0), XX1(2, 0), tid);
        float ss = mpo_last36_sq_r2(E_OFF, S_OFF, H1, tid);  // env_top raw -> E
        sumsq_publish(ss, tid);
        __syncthreads();
        float sc = read_scale();
        st_l0(H0, v, tid, sc);                           // n20 scaled
    }
    __syncthreads();

    // ================= Row 2 L-part =================
    {
        pf_full(vf, PB(2, 1), XX0(2, 1), XX1(2, 1), tid);
        mpo_first36(S_OFF, E_OFF, H0, tid);              // S <- env_top x n20
        st_full(H1, vf, tid);
    }
    __syncthreads();
    {
        float v = pf_slice36(PB(3, 0), XX0(3, 0), XX1(3, 0), 216, 36, tid); // (u,r)
        mpo_full_acc(acc36, S_OFF, H1, tid);
        __syncthreads();
        mpo_full_st(acc36, S_OFF, tid);                  // S = L2 (persists)
        st_id(H0, v, 36, tid);                           // n30
    }
    __syncthreads();

    // ================= Row 3 (P0/P1 ping-pong; S untouched) =================
    {
        float v = pf_d0(PB(3, 1), XX0(3, 1), XX1(3, 1), tid);   // [u][r][l]
        if (tid < 36) sm[P0 + tid] = sm[H0 + tid];
        st_id(H1, v, 216, tid);
    }
    __syncthreads();
    {
        float v = pf_d0(PB(3, 2), XX0(3, 2), XX1(3, 2), tid);
        rowstep(P1, P0, H1, 6, true, tid);
        st_id(H0, v, 216, tid);
    }
    __syncthreads();
    {
        float v = pf_slice36(PB(3, 3), XX0(3, 3), XX1(3, 3), 216, 1, tid);  // (u,l)
        rowstep(P0, P1, H0, 36, true, tid);
        st_id(H0 + 432, v, 36, tid);                     // n33 parked
    }
    __syncthreads();
    {
        float v = pf_r0(PB(2, 3), XX0(2, 3), XX1(2, 3), tid);   // n23 [u][d][l]
        float ss = laststep_T_sq_r2(E_OFF, P0, H0 + 432, tid);  // env_botT raw -> E
        sumsq_publish(ss, tid);
        __syncthreads();
        float sc = read_scale();
        st_n23(H1, v, tid, sc);                          // n23 scaled -> H1
    }
    __syncthreads();

    // ================= fused R + tgemm (in-place over S) =================
    step1_acc(acc36, S_OFF, E_OFF, tid);                 // reads S (L2) + E (env_botT)
    __syncthreads();
    step1_st(acc36, S_OFF, tid);                         // S = M
    __syncthreads();
    step2(E_OFF, S_OFF, H1, tid);                        // T -> E
    __syncthreads();

    // ================= Final contraction with peps_center (float4) ========
    {
        const float xc0 = XX0(2, 2);
        const float xc1 = XX1(2, 2);
        float acc[10];
        #pragma unroll
        for (int o = 0; o < 10; o++) acc[o] = 0.0f;
        for (int kk = tid * 4; kk < 1296; kk += NT * 4) {
            const float4 e4 = *(const float4*)(sm + E_OFF + kk);
            float4 e0 = make_float4(e4.x * xc0, e4.y * xc0, e4.z * xc0, e4.w * xc0);
            float4 e1 = make_float4(e4.x * xc1, e4.y * xc1, e4.z * xc1, e4.w * xc1);
            #pragma unroll
            for (int o = 0; o < 10; o++) {
                float4 p0 = __ldg((const float4*)(pepsc + o * 1296 + kk));
                float4 p1 = __ldg((const float4*)(pepsc + 12960 + o * 1296 + kk));
                acc[o] += e0.x * p0.x + e0.y * p0.y + e0.z * p0.z + e0.w * p0.w
                        + e1.x * p1.x + e1.y * p1.y + e1.z * p1.z + e1.w * p1.w;
            }
        }
        #pragma unroll
        for (int o = 0; o < 10; o++)
            #pragma unroll
            for (int off = 16; off > 0; off >>= 1)
                acc[o] += __shfl_down_sync(0xffffffffu, acc[o], off);
        const int w = tid >> 5;
        if ((tid & 31) == 0) {
            #pragma unroll
            for (int o = 0; o < 10; o++) sm[P0 + w * 10 + o] = acc[o];
        }
        __syncthreads();
        if (tid < 10) {
            float s = 0.0f;
            #pragma unroll
            for (int ww = 0; ww < 7; ww++) s += sm[P0 + ww * 10 + tid];
            sm[OFF_OUT + tid] = s;
        }
        __syncthreads();
    }

    if (tid < 10) {
        float nrm = 0.0f;
        #pragma unroll
        for (int o = 0; o < 10; o++) { float t = sm[OFF_OUT + o]; nrm += t * t; }
        out[b * 10 + tid] = sm[OFF_OUT + tid] * rsqrtf(nrm);
    }
}

// ---------------------------------------------------------------------------
// launch
// ---------------------------------------------------------------------------

extern "C" void kernel_launch(void* const* d_in, const int* in_sizes, int n_in,
                              void* d_out, int out_size)
{
    const float* inputs = (const float*)d_in[0];   // (B,4,4,2)
    const float* peps   = (const float*)d_in[1];   // (4,4,2,6,6,6,6)
    const float* pepsc  = (const float*)d_in[2];   // (2,10,6,6,6,6)
    float* out = (float*)d_out;                    // (B,10)

    const int B = in_sizes[0] / 32;

    cudaFuncSetAttribute(peps_forward_kernel,
                         cudaFuncAttributeMaxDynamicSharedMemorySize, SMEM_BYTES);
    peps_forward_kernel<<<B, NT, SMEM_BYTES>>>(inputs, peps, pepsc, out, B);
}